// round 12
// baseline (speedup 1.0000x reference)
#include <cuda_runtime.h>
#include <cuda_bf16.h>
#include <mma.h>
#include <cstdint>

using namespace nvcuda;

#define CC   128
#define BKT  8192
#define NMAX 500000

// ---------------- scratch (__device__ globals; no allocs allowed) ----------
__device__ float    g_q[(size_t)NMAX * CC];      // 256 MB
__device__ float    g_xsum[BKT * CC];
__device__ unsigned g_kkey[BKT * CC];
__device__ unsigned g_vkey[BKT * CC];
__device__ float    g_counts[BKT];
__device__ float    g_kc[BKT * 2 * CC];          // [k_mean | k_max] per bucket
__device__ float    g_vcomb[BKT * CC];           // [v_mean|v_max] @ Wvc + bvc
__device__ unsigned g_or;                        // 0 => ids are int64
__device__ int      g_hist[BKT];
__device__ int      g_cursor[BKT];
__device__ int      g_perm[NMAX];
// pre-split weights (bf16 hi/lo, row-major ldm=128)
__device__ __align__(256) __nv_bfloat16 g_wqh[128 * 128], g_wql[128 * 128];
__device__ __align__(256) __nv_bfloat16 g_wkh[128 * 128], g_wkl[128 * 128];
__device__ __align__(256) __nv_bfloat16 g_wvh[128 * 128], g_wvl[128 * 128];
__device__ __align__(256) __nv_bfloat16 g_wg1h[256 * 128], g_wg1l[256 * 128];
__device__ __align__(256) __nv_bfloat16 g_wg2h[128 * 128], g_wg2l[128 * 128];
__device__ __align__(256) __nv_bfloat16 g_wph[128 * 128],  g_wpl[128 * 128];

// monotonic float<->uint mapping for atomicMax on floats
__device__ __forceinline__ unsigned fenc(float f) {
    unsigned u = __float_as_uint(f);
    return (u & 0x80000000u) ? ~u : (u | 0x80000000u);
}
__device__ __forceinline__ float fdec(unsigned e) {
    return (e & 0x80000000u) ? __uint_as_float(e ^ 0x80000000u)
                             : __uint_as_float(~e);
}
__device__ __forceinline__ int get_id(const void* ids, int i, bool is64) {
    return is64 ? (int)((const long long*)ids)[i] : ((const int*)ids)[i];
}
__device__ __forceinline__ void bfsplit(float v, __nv_bfloat16& h, __nv_bfloat16& l) {
    h = __float2bfloat16(v);
    l = __float2bfloat16(v - __bfloat162float(h));
}

// ---------------- init ------------------------------------------------------
__global__ void k_init() {
    size_t i = (size_t)blockIdx.x * blockDim.x + threadIdx.x;
    size_t stride = (size_t)gridDim.x * blockDim.x;
    for (size_t t = i; t < (size_t)BKT * CC; t += stride) {
        g_xsum[t] = 0.0f; g_kkey[t] = 0u; g_vkey[t] = 0u;
    }
    for (size_t t = i; t < BKT; t += stride) { g_counts[t] = 0.0f; g_hist[t] = 0; }
    if (i == 0) g_or = 0u;
}

// ---------------- id dtype detection ---------------------------------------
__global__ void k_detect(const unsigned* __restrict__ w, int nwords) {
    unsigned acc = 0;
    int gid = blockIdx.x * blockDim.x + threadIdx.x;
    int stride = gridDim.x * blockDim.x;
    for (int t = 1 + 2 * gid; t < nwords; t += 2 * stride) acc |= w[t];
    for (int o = 16; o; o >>= 1) acc |= __shfl_xor_sync(0xFFFFFFFFu, acc, o);
    if ((threadIdx.x & 31) == 0 && acc) atomicOr(&g_or, acc);
}

// ---------------- counting sort: histogram, scan, scatter -------------------
__global__ void k_hist(const void* __restrict__ ids, int n) {
    const bool is64 = (g_or == 0u);
    int i = blockIdx.x * blockDim.x + threadIdx.x;
    if (i < n) atomicAdd(&g_hist[get_id(ids, i, is64)], 1);
}

__global__ void k_scan() {
    __shared__ int part[1024];
    int t = threadIdx.x;
    int loc[8];
    int s = 0;
    #pragma unroll
    for (int j = 0; j < 8; j++) { loc[j] = s; s += g_hist[t * 8 + j]; }
    part[t] = s;
    __syncthreads();
    for (int off = 1; off < 1024; off <<= 1) {
        int v = (t >= off) ? part[t - off] : 0;
        __syncthreads();
        part[t] += v;
        __syncthreads();
    }
    int base = (t > 0) ? part[t - 1] : 0;
    #pragma unroll
    for (int j = 0; j < 8; j++) g_cursor[t * 8 + j] = base + loc[j];
}

__global__ void k_scatter(const void* __restrict__ ids, int n) {
    const bool is64 = (g_or == 0u);
    int i = blockIdx.x * blockDim.x + threadIdx.x;
    if (i < n) {
        int b = get_id(ids, i, is64);
        int pos = atomicAdd(&g_cursor[b], 1);
        g_perm[pos] = i;
    }
}

// ---------------- weight prep: bf16 hi/lo splits (all six matrices) ---------
__global__ void k_prep(const float* __restrict__ Wq, const float* __restrict__ Wk,
                       const float* __restrict__ Wv, const float* __restrict__ Wg1,
                       const float* __restrict__ Wg2, const float* __restrict__ Wp) {
    int t = blockIdx.x * 256 + threadIdx.x;     // 114688 total
    if (t >= 114688) return;
    __nv_bfloat16 h, l;
    if (t < 16384) {
        bfsplit(Wq[t], h, l); g_wqh[t] = h; g_wql[t] = l;
    } else if (t < 32768) {
        int i = t - 16384;
        bfsplit(Wk[i], h, l); g_wkh[i] = h; g_wkl[i] = l;
    } else if (t < 49152) {
        int i = t - 32768;
        bfsplit(Wv[i], h, l); g_wvh[i] = h; g_wvl[i] = l;
    } else if (t < 81920) {
        int i = t - 49152;
        bfsplit(Wg1[i], h, l); g_wg1h[i] = h; g_wg1l[i] = l;
    } else if (t < 98304) {
        int i = t - 81920;
        bfsplit(Wg2[i], h, l); g_wg2h[i] = h; g_wg2l[i] = l;
    } else {
        int i = t - 98304;
        bfsplit(Wp[i], h, l);  g_wph[i] = h;  g_wpl[i] = l;
    }
}

// ---------------- phase 1: sorted wmma qkv GEMM + segmented reductions ------
#define QX_STR 136     // xs stride
#define QW_STR 136     // weight chunk stride
#define QO_STR 132     // f32 staging stride
#define SM_QKV_BYTES (2 * 64 * QX_STR * 2 + 2 * 16 * QW_STR * 2 + 64 * QO_STR * 4) // 77312

// Guarded Hillis-Steele segmented reduction over the 64-row tile (rows sorted
// by bucket, so equal keys are contiguous -> key[r]==key[r+s] validates the
// whole span). OP: 0 = max, 1 = add. All 256 threads must call.
template<int OP>
__device__ __forceinline__ void seg_reduce(float* outb, const int* ids_s,
                                           int ep_r, int ep_c0) {
    for (int s = 1; s < 64; s <<= 1) {
        float tmp[32];
        bool ok = (ep_r + s < 64) && (ids_s[ep_r] == ids_s[ep_r + s]);
        if (ok) {
            #pragma unroll
            for (int c = 0; c < 32; c += 4) {
                float4 t4 = *(const float4*)&outb[(ep_r + s) * QO_STR + ep_c0 + c];
                tmp[c] = t4.x; tmp[c + 1] = t4.y; tmp[c + 2] = t4.z; tmp[c + 3] = t4.w;
            }
        }
        __syncthreads();
        if (ok) {
            #pragma unroll
            for (int c = 0; c < 32; c += 4) {
                float4 cur = *(const float4*)&outb[ep_r * QO_STR + ep_c0 + c];
                float4 r;
                if (OP == 0) {
                    r.x = fmaxf(cur.x, tmp[c]);     r.y = fmaxf(cur.y, tmp[c + 1]);
                    r.z = fmaxf(cur.z, tmp[c + 2]); r.w = fmaxf(cur.w, tmp[c + 3]);
                } else {
                    r.x = cur.x + tmp[c];     r.y = cur.y + tmp[c + 1];
                    r.z = cur.z + tmp[c + 2]; r.w = cur.w + tmp[c + 3];
                }
                *(float4*)&outb[ep_r * QO_STR + ep_c0 + c] = r;
            }
        }
        __syncthreads();
    }
}

__global__ void __launch_bounds__(256, 2)
k_qkv(const float* __restrict__ x, const void* __restrict__ ids,
      const float* __restrict__ bq, const float* __restrict__ bk,
      const float* __restrict__ bv, int n) {
    extern __shared__ unsigned char smraw[];
    __nv_bfloat16* xs_hi = (__nv_bfloat16*)smraw;                  // 64*136
    __nv_bfloat16* xs_lo = xs_hi + 64 * QX_STR;
    __nv_bfloat16* wsh   = xs_lo + 64 * QX_STR;                    // 16*136
    __nv_bfloat16* wsl   = wsh + 16 * QW_STR;
    float*         outb  = (float*)(wsl + 16 * QW_STR);            // 64*132
    __shared__ int ids_s[64];
    __shared__ int perm_s[64];
    __shared__ float s_b[3][128];

    const bool is64 = (g_or == 0u);
    const int tid = threadIdx.x;
    const int wid = tid >> 5;
    const int row0 = blockIdx.x * 64;
    const int wr = wid >> 1;            // rows wr*16
    const int wc = wid & 1;             // cols wc*64
    const int ep_r = tid >> 2;          // 0..63
    const int ep_c0 = (tid & 3) * 32;   // 32 cols

    if (tid < 64) {
        int p = row0 + tid;
        int r = -1, b = -1;
        if (p < n) { r = g_perm[p]; b = get_id(ids, r, is64); }
        perm_s[tid] = r;
        ids_s[tid] = b;
    }
    if (tid < 128) {
        s_b[0][tid] = bq[tid]; s_b[1][tid] = bk[tid]; s_b[2][tid] = bv[tid];
    }
    __syncthreads();

    // gather x rows (sorted order) -> bf16 hi/lo
    for (int t = tid; t < 64 * 32; t += 256) {
        int r = t >> 5, c4 = t & 31;
        int gr = perm_s[r];
        float4 v = make_float4(0.f, 0.f, 0.f, 0.f);
        if (gr >= 0) v = ((const float4*)x)[(size_t)gr * 32 + c4];
        float vv[4] = {v.x, v.y, v.z, v.w};
        #pragma unroll
        for (int j = 0; j < 4; j++) {
            __nv_bfloat16 h, l;
            bfsplit(vv[j], h, l);
            xs_hi[r * QX_STR + c4 * 4 + j] = h;
            xs_lo[r * QX_STR + c4 * 4 + j] = l;
        }
    }

    const bool head = (ep_r == 0) || (ids_s[ep_r] != ids_s[(ep_r > 0) ? ep_r - 1 : 0]);

    for (int mm = 0; mm < 3; mm++) {
        const __nv_bfloat16* Wh = (mm == 0) ? g_wqh : (mm == 1) ? g_wkh : g_wvh;
        const __nv_bfloat16* Wl = (mm == 0) ? g_wql : (mm == 1) ? g_wkl : g_wvl;

        wmma::fragment<wmma::accumulator, 16, 16, 16, float> acc[4];
        #pragma unroll
        for (int j = 0; j < 4; j++) wmma::fill_fragment(acc[j], 0.0f);

        for (int ks = 0; ks < 8; ks++) {
            int k0 = ks * 16;
            __syncthreads();   // xs writes (first) / prior chunk reads / epi outb reads
            {
                int r = tid >> 4, c16 = tid & 15;
                *(uint4*)&wsh[r * QW_STR + c16 * 8] = ((const uint4*)&Wh[(k0 + r) * 128])[c16];
                *(uint4*)&wsl[r * QW_STR + c16 * 8] = ((const uint4*)&Wl[(k0 + r) * 128])[c16];
            }
            __syncthreads();
            wmma::fragment<wmma::matrix_a, 16, 16, 16, __nv_bfloat16, wmma::row_major> ah, al;
            wmma::load_matrix_sync(ah, &xs_hi[(wr * 16) * QX_STR + k0], QX_STR);
            wmma::load_matrix_sync(al, &xs_lo[(wr * 16) * QX_STR + k0], QX_STR);
            #pragma unroll
            for (int j = 0; j < 4; j++) {
                wmma::fragment<wmma::matrix_b, 16, 16, 16, __nv_bfloat16, wmma::row_major> bh, bl;
                wmma::load_matrix_sync(bh, &wsh[wc * 64 + j * 16], QW_STR);
                wmma::load_matrix_sync(bl, &wsl[wc * 64 + j * 16], QW_STR);
                wmma::mma_sync(acc[j], ah, bh, acc[j]);
                wmma::mma_sync(acc[j], ah, bl, acc[j]);
                wmma::mma_sync(acc[j], al, bh, acc[j]);
            }
        }
        __syncthreads();   // ws reads done; prior epilogue outb reads done
        #pragma unroll
        for (int j = 0; j < 4; j++)
            wmma::store_matrix_sync(&outb[(wr * 16) * QO_STR + wc * 64 + j * 16],
                                    acc[j], QO_STR, wmma::mem_row_major);
        __syncthreads();

        if (mm == 0) {
            // q: scatter back to original row
            int grow = perm_s[ep_r];
            if (grow >= 0) {
                float* qp = &g_q[(size_t)grow * 128];
                #pragma unroll
                for (int c = 0; c < 32; c += 4) {
                    int cc = ep_c0 + c;
                    float4 o = *(const float4*)&outb[ep_r * QO_STR + cc];
                    *(float4*)&qp[cc] = make_float4(o.x + s_b[0][cc], o.y + s_b[0][cc + 1],
                                                    o.z + s_b[0][cc + 2], o.w + s_b[0][cc + 3]);
                }
            }
        } else {
            // segmented max within tile, then one atomic per segment head
            seg_reduce<0>(outb, ids_s, ep_r, ep_c0);
            int b = ids_s[ep_r];
            if (head && b >= 0) {
                unsigned* p = ((mm == 1) ? g_kkey : g_vkey) + (size_t)b * 128;
                #pragma unroll 8
                for (int c = 0; c < 32; c++) {
                    int cc = ep_c0 + c;
                    atomicMax(&p[cc], fenc(outb[ep_r * QO_STR + cc] + s_b[mm][cc]));
                }
            }
        }
    }

    // x_sum + counts via segmented add
    __syncthreads();   // epilogue outb reads done
    #pragma unroll 8
    for (int c = 0; c < 32; c++) {
        int cc = ep_c0 + c;
        outb[ep_r * QO_STR + cc] = __bfloat162float(xs_hi[ep_r * QX_STR + cc])
                                 + __bfloat162float(xs_lo[ep_r * QX_STR + cc]);
    }
    __syncthreads();
    seg_reduce<1>(outb, ids_s, ep_r, ep_c0);
    {
        int b = ids_s[ep_r];
        if (head && b >= 0) {
            float* dst = &g_xsum[(size_t)b * 128];
            #pragma unroll 8
            for (int c = 0; c < 32; c++) {
                int cc = ep_c0 + c;
                atomicAdd(&dst[cc], outb[ep_r * QO_STR + cc]);
            }
            if ((tid & 3) == 0) {
                int len = 0;
                while (ep_r + len < 64 && ids_s[ep_r + len] == b) len++;
                atomicAdd(&g_counts[b], (float)len);
            }
        }
    }
}

// ---------------- phase 2: centroid finalize + per-bucket Wvc GEMM ----------
__global__ void __launch_bounds__(256)
k_cent(const float* __restrict__ Wk,  const float* __restrict__ bk,
       const float* __restrict__ Wv,  const float* __restrict__ bv,
       const float* __restrict__ Wvc, const float* __restrict__ bvc) {
    __shared__ float vt[2][256];
    int tid = threadIdx.x;
    int bl = tid >> 7, c = tid & 127;
    int b = blockIdx.x * 2 + bl;

    float cnt = g_counts[b];
    float inv = 1.0f / fmaxf(cnt, 1.0f);
    const float* xs = &g_xsum[(size_t)b * 128];
    float ak = 0.0f, av = 0.0f;
    #pragma unroll 4
    for (int k = 0; k < 128; k++) {
        float xv = xs[k];
        ak = fmaf(xv, __ldg(&Wk[k * 128 + c]), ak);
        av = fmaf(xv, __ldg(&Wv[k * 128 + c]), av);
    }
    float kmean = (ak + cnt * __ldg(&bk[c])) * inv;
    float vmean = (av + cnt * __ldg(&bv[c])) * inv;
    bool ne = cnt > 0.0f;
    float kmax = ne ? fdec(g_kkey[(size_t)b * 128 + c]) : 0.0f;
    float vmax = ne ? fdec(g_vkey[(size_t)b * 128 + c]) : 0.0f;

    g_kc[(size_t)b * 256 + c]       = kmean;
    g_kc[(size_t)b * 256 + 128 + c] = kmax;
    vt[bl][c]       = vmean;
    vt[bl][128 + c] = vmax;
    __syncthreads();

    float a = 0.0f;
    #pragma unroll 4
    for (int k = 0; k < 256; k++)
        a = fmaf(vt[bl][k], __ldg(&Wvc[k * 128 + c]), a);
    g_vcomb[(size_t)b * 128 + c] = a + __ldg(&bvc[c]);
}

// ---------------- phase 3: wmma bf16-split fused chain (R10/R11 winner) -----
#define I_STR 264
#define H_STR 136
#define FO_STR 132
#define W_STR 136
#define RGN 34816
#define SM_FUSED_BYTES (3 * RGN + 2 * 16 * W_STR * 2)   // 113152

__global__ void __launch_bounds__(256, 2)
k_fused(const void* __restrict__ ids,
        const float* __restrict__ bg1, const float* __restrict__ bg2,
        const float* __restrict__ bp,  float* __restrict__ out, int n) {
    extern __shared__ unsigned char smraw[];
    __nv_bfloat16* ih  = (__nv_bfloat16*)(smraw);            // 64*264
    __nv_bfloat16* il  = (__nv_bfloat16*)(smraw + RGN);      // 64*264
    __nv_bfloat16* h1h = (__nv_bfloat16*)(smraw + 2 * RGN);  // 64*136
    __nv_bfloat16* h1l = h1h + 64 * H_STR;
    float*        outb = (float*)(smraw);                    // reuse RA
    __nv_bfloat16* tbh = (__nv_bfloat16*)(smraw + RGN);      // reuse RB
    __nv_bfloat16* tbl = tbh + 64 * H_STR;
    __nv_bfloat16* wsh = (__nv_bfloat16*)(smraw + 3 * RGN);  // 16*136
    __nv_bfloat16* wsl = wsh + 16 * W_STR;
    __shared__ int ids_s[64];

    const bool is64 = (g_or == 0u);
    const int tid = threadIdx.x;
    const int wid = tid >> 5;
    const int row0 = blockIdx.x * 64;
    const float scale = 0.17677669529663687f;   // (128/4)^-0.5
    const int wr = wid >> 1;
    const int wc = wid & 1;
    const int ep_r = tid >> 2;
    const int ep_c0 = (tid & 3) * 32;

    if (tid < 64) {
        int r = row0 + tid;
        ids_s[tid] = (r < n) ? get_id(ids, r, is64) : -1;
    }
    __syncthreads();

    // stage a: inter = [q,q]*kctx*scale -> bf16 hi/lo
    for (int t = tid; t < 64 * 64; t += 256) {
        int r = t >> 6, c4 = t & 63;
        int b = ids_s[r];
        float4 iv = make_float4(0.f, 0.f, 0.f, 0.f);
        if (b >= 0) {
            float4 qv = ((const float4*)g_q)[(size_t)(row0 + r) * 32 + (c4 & 31)];
            float4 kc = ((const float4*)g_kc)[(size_t)b * 64 + c4];
            iv.x = qv.x * kc.x * scale; iv.y = qv.y * kc.y * scale;
            iv.z = qv.z * kc.z * scale; iv.w = qv.w * kc.w * scale;
        }
        float vv[4] = {iv.x, iv.y, iv.z, iv.w};
        #pragma unroll
        for (int j = 0; j < 4; j++) {
            __nv_bfloat16 h, l;
            bfsplit(vv[j], h, l);
            ih[r * I_STR + c4 * 4 + j] = h;
            il[r * I_STR + c4 * 4 + j] = l;
        }
    }

    wmma::fragment<wmma::accumulator, 16, 16, 16, float> acc[4];

    // ---- GEMM1: h1 = relu(inter @ Wg1 + bg1), K=256 ----
    #pragma unroll
    for (int j = 0; j < 4; j++) wmma::fill_fragment(acc[j], 0.0f);
    for (int ks = 0; ks < 16; ks++) {
        int k0 = ks * 16;
        __syncthreads();
        {
            int r = tid >> 4, c16 = tid & 15;
            *(uint4*)&wsh[r * W_STR + c16 * 8] = ((const uint4*)&g_wg1h[(k0 + r) * 128])[c16];
            *(uint4*)&wsl[r * W_STR + c16 * 8] = ((const uint4*)&g_wg1l[(k0 + r) * 128])[c16];
        }
        __syncthreads();
        wmma::fragment<wmma::matrix_a, 16, 16, 16, __nv_bfloat16, wmma::row_major> ah, al;
        wmma::load_matrix_sync(ah, &ih[(wr * 16) * I_STR + k0], I_STR);
        wmma::load_matrix_sync(al, &il[(wr * 16) * I_STR + k0], I_STR);
        #pragma unroll
        for (int j = 0; j < 4; j++) {
            wmma::fragment<wmma::matrix_b, 16, 16, 16, __nv_bfloat16, wmma::row_major> bh, bl;
            wmma::load_matrix_sync(bh, &wsh[wc * 64 + j * 16], W_STR);
            wmma::load_matrix_sync(bl, &wsl[wc * 64 + j * 16], W_STR);
            wmma::mma_sync(acc[j], ah, bh, acc[j]);
            wmma::mma_sync(acc[j], ah, bl, acc[j]);
            wmma::mma_sync(acc[j], al, bh, acc[j]);
        }
    }
    __syncthreads();
    #pragma unroll
    for (int j = 0; j < 4; j++)
        wmma::store_matrix_sync(&outb[(wr * 16) * FO_STR + wc * 64 + j * 16],
                                acc[j], FO_STR, wmma::mem_row_major);
    __syncthreads();
    #pragma unroll 8
    for (int c = 0; c < 32; c++) {
        int cc = ep_c0 + c;
        float v = fmaxf(outb[ep_r * FO_STR + cc] + __ldg(&bg1[cc]), 0.0f);
        __nv_bfloat16 h, l;
        bfsplit(v, h, l);
        h1h[ep_r * H_STR + cc] = h;
        h1l[ep_r * H_STR + cc] = l;
    }

    // ---- GEMM2: gate = sigmoid(h1 @ Wg2 + bg2); tbuf = gate * vcomb ----
    #pragma unroll
    for (int j = 0; j < 4; j++) wmma::fill_fragment(acc[j], 0.0f);
    for (int ks = 0; ks < 8; ks++) {
        int k0 = ks * 16;
        __syncthreads();
        {
            int r = tid >> 4, c16 = tid & 15;
            *(uint4*)&wsh[r * W_STR + c16 * 8] = ((const uint4*)&g_wg2h[(k0 + r) * 128])[c16];
            *(uint4*)&wsl[r * W_STR + c16 * 8] = ((const uint4*)&g_wg2l[(k0 + r) * 128])[c16];
        }
        __syncthreads();
        wmma::fragment<wmma::matrix_a, 16, 16, 16, __nv_bfloat16, wmma::row_major> ah, al;
        wmma::load_matrix_sync(ah, &h1h[(wr * 16) * H_STR + k0], H_STR);
        wmma::load_matrix_sync(al, &h1l[(wr * 16) * H_STR + k0], H_STR);
        #pragma unroll
        for (int j = 0; j < 4; j++) {
            wmma::fragment<wmma::matrix_b, 16, 16, 16, __nv_bfloat16, wmma::row_major> bh, bl;
            wmma::load_matrix_sync(bh, &wsh[wc * 64 + j * 16], W_STR);
            wmma::load_matrix_sync(bl, &wsl[wc * 64 + j * 16], W_STR);
            wmma::mma_sync(acc[j], ah, bh, acc[j]);
            wmma::mma_sync(acc[j], ah, bl, acc[j]);
            wmma::mma_sync(acc[j], al, bh, acc[j]);
        }
    }
    __syncthreads();
    #pragma unroll
    for (int j = 0; j < 4; j++)
        wmma::store_matrix_sync(&outb[(wr * 16) * FO_STR + wc * 64 + j * 16],
                                acc[j], FO_STR, wmma::mem_row_major);
    __syncthreads();
    {
        int b = ids_s[ep_r];
        #pragma unroll 8
        for (int c = 0; c < 32; c++) {
            int cc = ep_c0 + c;
            float gate = 1.0f / (1.0f + __expf(-(outb[ep_r * FO_STR + cc] + __ldg(&bg2[cc]))));
            float vc = (b >= 0) ? g_vcomb[(size_t)b * 128 + cc] : 0.0f;
            __nv_bfloat16 h, l;
            bfsplit(gate * vc, h, l);
            tbh[ep_r * H_STR + cc] = h;
            tbl[ep_r * H_STR + cc] = l;
        }
    }

    // ---- GEMM3: out = tbuf @ Wp + bp ----
    #pragma unroll
    for (int j = 0; j < 4; j++) wmma::fill_fragment(acc[j], 0.0f);
    for (int ks = 0; ks < 8; ks++) {
        int k0 = ks * 16;
        __syncthreads();
        {
            int r = tid >> 4, c16 = tid & 15;
            *(uint4*)&wsh[r * W_STR + c16 * 8] = ((const uint4*)&g_wph[(k0 + r) * 128])[c16];
            *(uint4*)&wsl[r * W_STR + c16 * 8] = ((const uint4*)&g_wpl[(k0 + r) * 128])[c16];
        }
        __syncthreads();
        wmma::fragment<wmma::matrix_a, 16, 16, 16, __nv_bfloat16, wmma::row_major> ah, al;
        wmma::load_matrix_sync(ah, &tbh[(wr * 16) * H_STR + k0], H_STR);
        wmma::load_matrix_sync(al, &tbl[(wr * 16) * H_STR + k0], H_STR);
        #pragma unroll
        for (int j = 0; j < 4; j++) {
            wmma::fragment<wmma::matrix_b, 16, 16, 16, __nv_bfloat16, wmma::row_major> bh, bl;
            wmma::load_matrix_sync(bh, &wsh[wc * 64 + j * 16], W_STR);
            wmma::load_matrix_sync(bl, &wsl[wc * 64 + j * 16], W_STR);
            wmma::mma_sync(acc[j], ah, bh, acc[j]);
            wmma::mma_sync(acc[j], ah, bl, acc[j]);
            wmma::mma_sync(acc[j], al, bh, acc[j]);
        }
    }
    __syncthreads();
    #pragma unroll
    for (int j = 0; j < 4; j++)
        wmma::store_matrix_sync(&outb[(wr * 16) * FO_STR + wc * 64 + j * 16],
                                acc[j], FO_STR, wmma::mem_row_major);
    __syncthreads();
    {
        int grow = row0 + ep_r;
        if (grow < n) {
            float* op = &out[(size_t)grow * 128];
            #pragma unroll
            for (int c = 0; c < 32; c += 4) {
                int cc = ep_c0 + c;
                float4 o = *(const float4*)&outb[ep_r * FO_STR + cc];
                float4 b4 = *(const float4*)&bp[cc];
                *(float4*)&op[cc] = make_float4(o.x + b4.x, o.y + b4.y,
                                                o.z + b4.z, o.w + b4.w);
            }
        }
    }
}

// ---------------- launch ----------------------------------------------------
extern "C" void kernel_launch(void* const* d_in, const int* in_sizes, int n_in,
                              void* d_out, int out_size) {
    const float* x   = (const float*)d_in[0];
    const void*  ids = d_in[1];
    // d_in[2] = total_buckets (constant 8192, unused)
    const float *Wq = (const float*)d_in[3],  *bq = (const float*)d_in[4];
    const float *Wk = (const float*)d_in[5],  *bk = (const float*)d_in[6];
    const float *Wv = (const float*)d_in[7],  *bv = (const float*)d_in[8];
    const float *Wg1 = (const float*)d_in[9], *bg1 = (const float*)d_in[10];
    const float *Wg2 = (const float*)d_in[11], *bg2 = (const float*)d_in[12];
    const float *Wvc = (const float*)d_in[13], *bvc = (const float*)d_in[14];
    const float *Wp  = (const float*)d_in[15], *bp  = (const float*)d_in[16];
    float* out = (float*)d_out;

    const int n = in_sizes[0] / CC;

    static int smem_set = 0;
    if (!smem_set) {
        cudaFuncSetAttribute(k_qkv,   cudaFuncAttributeMaxDynamicSharedMemorySize, SM_QKV_BYTES);
        cudaFuncSetAttribute(k_fused, cudaFuncAttributeMaxDynamicSharedMemorySize, SM_FUSED_BYTES);
        smem_set = 1;
    }

    k_init<<<512, 256>>>();
    k_detect<<<256, 256>>>((const unsigned*)ids, in_sizes[1]);
    k_prep<<<448, 256>>>(Wq, Wk, Wv, Wg1, Wg2, Wp);

    int gthr = (n + 255) / 256;
    k_hist<<<gthr, 256>>>(ids, n);
    k_scan<<<1, 1024>>>();
    k_scatter<<<gthr, 256>>>(ids, n);

    int g1 = (n + 63) / 64;
    k_qkv<<<g1, 256, SM_QKV_BYTES>>>(x, ids, bq, bk, bv, n);

    k_cent<<<BKT / 2, 256>>>(Wk, bk, Wv, bv, Wvc, bvc);

    k_fused<<<g1, 256, SM_FUSED_BYTES>>>(ids, bg1, bg2, bp, out, n);
}

// round 13
// speedup vs baseline: 1.1560x; 1.1560x over previous
#include <cuda_runtime.h>
#include <cuda_bf16.h>
#include <mma.h>
#include <cstdint>

using namespace nvcuda;

#define CC   128
#define BKT  8192
#define NMAX 500000

// ---------------- scratch (__device__ globals; no allocs allowed) ----------
__device__ float    g_q[(size_t)NMAX * CC];      // 256 MB
__device__ float    g_xsum[BKT * CC];
__device__ unsigned g_kkey[BKT * CC];
__device__ unsigned g_vkey[BKT * CC];
__device__ float    g_counts[BKT];
__device__ float    g_kc[BKT * 2 * CC];          // [k_mean | k_max] per bucket
__device__ float    g_vcomb[BKT * CC];           // [v_mean|v_max] @ Wvc + bvc
__device__ unsigned g_or;                        // 0 => ids are int64
// pre-split weights (bf16 hi/lo, row-major ldm=128)
__device__ __align__(256) __nv_bfloat16 g_wqh[128 * 128], g_wql[128 * 128];
__device__ __align__(256) __nv_bfloat16 g_wkh[128 * 128], g_wkl[128 * 128];
__device__ __align__(256) __nv_bfloat16 g_wvh[128 * 128], g_wvl[128 * 128];
__device__ __align__(256) __nv_bfloat16 g_wg1h[256 * 128], g_wg1l[256 * 128];
__device__ __align__(256) __nv_bfloat16 g_wg2h[128 * 128], g_wg2l[128 * 128];
__device__ __align__(256) __nv_bfloat16 g_wph[128 * 128],  g_wpl[128 * 128];

// monotonic float<->uint mapping for atomicMax on floats
__device__ __forceinline__ unsigned fenc(float f) {
    unsigned u = __float_as_uint(f);
    return (u & 0x80000000u) ? ~u : (u | 0x80000000u);
}
__device__ __forceinline__ float fdec(unsigned e) {
    return (e & 0x80000000u) ? __uint_as_float(e ^ 0x80000000u)
                             : __uint_as_float(~e);
}
__device__ __forceinline__ int get_id(const void* ids, int i, bool is64) {
    return is64 ? (int)((const long long*)ids)[i] : ((const int*)ids)[i];
}
__device__ __forceinline__ void bfsplit(float v, __nv_bfloat16& h, __nv_bfloat16& l) {
    h = __float2bfloat16(v);
    l = __float2bfloat16(v - __bfloat162float(h));
}

// ---------------- init ------------------------------------------------------
__global__ void k_init() {
    size_t i = (size_t)blockIdx.x * blockDim.x + threadIdx.x;
    size_t stride = (size_t)gridDim.x * blockDim.x;
    for (size_t t = i; t < (size_t)BKT * CC; t += stride) {
        g_xsum[t] = 0.0f; g_kkey[t] = 0u; g_vkey[t] = 0u;
    }
    for (size_t t = i; t < BKT; t += stride) g_counts[t] = 0.0f;
    if (i == 0) g_or = 0u;
}

// ---------------- id dtype detection ---------------------------------------
__global__ void k_detect(const unsigned* __restrict__ w, int nwords) {
    unsigned acc = 0;
    int gid = blockIdx.x * blockDim.x + threadIdx.x;
    int stride = gridDim.x * blockDim.x;
    for (int t = 1 + 2 * gid; t < nwords; t += 2 * stride) acc |= w[t];
    for (int o = 16; o; o >>= 1) acc |= __shfl_xor_sync(0xFFFFFFFFu, acc, o);
    if ((threadIdx.x & 31) == 0 && acc) atomicOr(&g_or, acc);
}

// ---------------- weight prep: bf16 hi/lo splits (all six matrices) ---------
__global__ void k_prep(const float* __restrict__ Wq, const float* __restrict__ Wk,
                       const float* __restrict__ Wv, const float* __restrict__ Wg1,
                       const float* __restrict__ Wg2, const float* __restrict__ Wp) {
    int t = blockIdx.x * 256 + threadIdx.x;     // 114688 total
    if (t >= 114688) return;
    __nv_bfloat16 h, l;
    if (t < 16384) {
        bfsplit(Wq[t], h, l); g_wqh[t] = h; g_wql[t] = l;
    } else if (t < 32768) {
        int i = t - 16384;
        bfsplit(Wk[i], h, l); g_wkh[i] = h; g_wkl[i] = l;
    } else if (t < 49152) {
        int i = t - 32768;
        bfsplit(Wv[i], h, l); g_wvh[i] = h; g_wvl[i] = l;
    } else if (t < 81920) {
        int i = t - 49152;
        bfsplit(Wg1[i], h, l); g_wg1h[i] = h; g_wg1l[i] = l;
    } else if (t < 98304) {
        int i = t - 81920;
        bfsplit(Wg2[i], h, l); g_wg2h[i] = h; g_wg2l[i] = l;
    } else {
        int i = t - 98304;
        bfsplit(Wp[i], h, l);  g_wph[i] = h;  g_wpl[i] = l;
    }
}

// ---------------- phase 1: wmma qkv GEMM + reductions (pipelined staging) ---
// 64-row tile, 256 threads = 8 warps; warp out-tile 16x64. Weight chunks
// (16 k-rows hi+lo) register-prefetched one chunk ahead, flattened across
// the three matrices (24 chunks). 2 CTAs/SM.
#define QX_STR 136
#define QW_STR 136
#define QO_STR 132
#define SM_QKV_BYTES (2 * 64 * QX_STR * 2 + 2 * 16 * QW_STR * 2 + 64 * QO_STR * 4) // 77312

__global__ void __launch_bounds__(256, 2)
k_qkv(const float* __restrict__ x, const void* __restrict__ ids,
      const float* __restrict__ bq, const float* __restrict__ bk,
      const float* __restrict__ bv, int n) {
    extern __shared__ unsigned char smraw[];
    __nv_bfloat16* xs_hi = (__nv_bfloat16*)smraw;                  // 64*136
    __nv_bfloat16* xs_lo = xs_hi + 64 * QX_STR;
    __nv_bfloat16* wsh   = xs_lo + 64 * QX_STR;                    // 16*136
    __nv_bfloat16* wsl   = wsh + 16 * QW_STR;
    float*         outb  = (float*)(wsl + 16 * QW_STR);            // 64*132
    __shared__ int ids_s[64];
    __shared__ float s_b[3][128];

    const bool is64 = (g_or == 0u);
    const int tid = threadIdx.x;
    const int wid = tid >> 5;
    const int row0 = blockIdx.x * 64;
    const int wr = wid >> 1;            // rows wr*16
    const int wc = wid & 1;             // cols wc*64
    const int ep_r = tid >> 2;          // 0..63
    const int ep_c0 = (tid & 3) * 32;   // 32 cols
    const int prow = tid >> 4;          // staging row 0..15
    const int pcol = tid & 15;          // staging uint4 col

    const __nv_bfloat16* WHs[3] = {g_wqh, g_wkh, g_wvh};
    const __nv_bfloat16* WLs[3] = {g_wql, g_wkl, g_wvl};

    if (tid < 64) {
        int r = row0 + tid;
        ids_s[tid] = (r < n) ? get_id(ids, r, is64) : -1;
    }
    if (tid < 128) {
        s_b[0][tid] = bq[tid]; s_b[1][tid] = bk[tid]; s_b[2][tid] = bv[tid];
    }

    // prefetch weight chunk 0 (overlaps with x conversion below)
    uint4 ph = ((const uint4*)WHs[0])[prow * 16 + pcol];
    uint4 pl = ((const uint4*)WLs[0])[prow * 16 + pcol];

    // x tile -> bf16 hi/lo
    for (int t = tid; t < 64 * 32; t += 256) {
        int r = t >> 5, c4 = t & 31;
        float4 v = make_float4(0.f, 0.f, 0.f, 0.f);
        if (row0 + r < n) v = ((const float4*)x)[(size_t)(row0 + r) * 32 + c4];
        float vv[4] = {v.x, v.y, v.z, v.w};
        #pragma unroll
        for (int j = 0; j < 4; j++) {
            __nv_bfloat16 h, l;
            bfsplit(vv[j], h, l);
            xs_hi[r * QX_STR + c4 * 4 + j] = h;
            xs_lo[r * QX_STR + c4 * 4 + j] = l;
        }
    }
    __syncthreads();
    *(uint4*)&wsh[prow * QW_STR + pcol * 8] = ph;
    *(uint4*)&wsl[prow * QW_STR + pcol * 8] = pl;
    __syncthreads();

    wmma::fragment<wmma::accumulator, 16, 16, 16, float> acc[4];

    for (int t = 0; t < 24; t++) {
        const int mm = t >> 3, ks = t & 7, k0 = ks * 16;
        if (ks == 0) {
            #pragma unroll
            for (int j = 0; j < 4; j++) wmma::fill_fragment(acc[j], 0.0f);
        }
        if (t + 1 < 24) {   // prefetch next chunk into registers (overlaps MMA)
            int m2 = (t + 1) >> 3, k2 = ((t + 1) & 7) * 16;
            ph = ((const uint4*)WHs[m2])[(k2 + prow) * 16 + pcol];
            pl = ((const uint4*)WLs[m2])[(k2 + prow) * 16 + pcol];
        }
        {
            wmma::fragment<wmma::matrix_a, 16, 16, 16, __nv_bfloat16, wmma::row_major> ah, al;
            wmma::load_matrix_sync(ah, &xs_hi[(wr * 16) * QX_STR + k0], QX_STR);
            wmma::load_matrix_sync(al, &xs_lo[(wr * 16) * QX_STR + k0], QX_STR);
            #pragma unroll
            for (int j = 0; j < 4; j++) {
                wmma::fragment<wmma::matrix_b, 16, 16, 16, __nv_bfloat16, wmma::row_major> bh, bl;
                wmma::load_matrix_sync(bh, &wsh[wc * 64 + j * 16], QW_STR);
                wmma::load_matrix_sync(bl, &wsl[wc * 64 + j * 16], QW_STR);
                wmma::mma_sync(acc[j], ah, bh, acc[j]);
                wmma::mma_sync(acc[j], ah, bl, acc[j]);
                wmma::mma_sync(acc[j], al, bh, acc[j]);
            }
        }
        __syncthreads();   // wbuf reads done
        if (t + 1 < 24) {
            *(uint4*)&wsh[prow * QW_STR + pcol * 8] = ph;
            *(uint4*)&wsl[prow * QW_STR + pcol * 8] = pl;
        }
        if (ks == 7) {
            #pragma unroll
            for (int j = 0; j < 4; j++)
                wmma::store_matrix_sync(&outb[(wr * 16) * QO_STR + wc * 64 + j * 16],
                                        acc[j], QO_STR, wmma::mem_row_major);
        }
        __syncthreads();   // wbuf/outb writes visible

        if (ks == 7) {
            if (mm == 0) {
                int grow = row0 + ep_r;
                if (grow < n) {
                    float* qp = &g_q[(size_t)grow * 128];
                    #pragma unroll
                    for (int c = 0; c < 32; c += 4) {
                        int cc = ep_c0 + c;
                        float4 o = *(const float4*)&outb[ep_r * QO_STR + cc];
                        *(float4*)&qp[cc] = make_float4(o.x + s_b[0][cc], o.y + s_b[0][cc + 1],
                                                        o.z + s_b[0][cc + 2], o.w + s_b[0][cc + 3]);
                    }
                }
            } else {
                int b = ids_s[ep_r];
                if (b >= 0) {
                    unsigned* p = ((mm == 1) ? g_kkey : g_vkey) + (size_t)b * 128;
                    #pragma unroll 8
                    for (int c = 0; c < 32; c++) {
                        int cc = ep_c0 + c;
                        atomicMax(&p[cc], fenc(outb[ep_r * QO_STR + cc] + s_b[mm][cc]));
                    }
                }
            }
        }
    }

    // x_sum + counts (xs never overwritten)
    {
        int b = ids_s[ep_r];
        if (b >= 0) {
            float* dst = &g_xsum[(size_t)b * 128];
            #pragma unroll 8
            for (int c = 0; c < 32; c++) {
                int cc = ep_c0 + c;
                float v = __bfloat162float(xs_hi[ep_r * QX_STR + cc])
                        + __bfloat162float(xs_lo[ep_r * QX_STR + cc]);
                atomicAdd(&dst[cc], v);
            }
            if ((tid & 3) == 0) atomicAdd(&g_counts[b], 1.0f);
        }
    }
}

// ---------------- phase 2: centroid finalize + per-bucket Wvc GEMM ----------
__global__ void __launch_bounds__(256)
k_cent(const float* __restrict__ Wk,  const float* __restrict__ bk,
       const float* __restrict__ Wv,  const float* __restrict__ bv,
       const float* __restrict__ Wvc, const float* __restrict__ bvc) {
    __shared__ float vt[2][256];
    int tid = threadIdx.x;
    int bl = tid >> 7, c = tid & 127;
    int b = blockIdx.x * 2 + bl;

    float cnt = g_counts[b];
    float inv = 1.0f / fmaxf(cnt, 1.0f);
    const float* xs = &g_xsum[(size_t)b * 128];
    float ak = 0.0f, av = 0.0f;
    #pragma unroll 4
    for (int k = 0; k < 128; k++) {
        float xv = xs[k];
        ak = fmaf(xv, __ldg(&Wk[k * 128 + c]), ak);
        av = fmaf(xv, __ldg(&Wv[k * 128 + c]), av);
    }
    float kmean = (ak + cnt * __ldg(&bk[c])) * inv;
    float vmean = (av + cnt * __ldg(&bv[c])) * inv;
    bool ne = cnt > 0.0f;
    float kmax = ne ? fdec(g_kkey[(size_t)b * 128 + c]) : 0.0f;
    float vmax = ne ? fdec(g_vkey[(size_t)b * 128 + c]) : 0.0f;

    g_kc[(size_t)b * 256 + c]       = kmean;
    g_kc[(size_t)b * 256 + 128 + c] = kmax;
    vt[bl][c]       = vmean;
    vt[bl][128 + c] = vmax;
    __syncthreads();

    float a = 0.0f;
    #pragma unroll 4
    for (int k = 0; k < 256; k++)
        a = fmaf(vt[bl][k], __ldg(&Wvc[k * 128 + c]), a);
    g_vcomb[(size_t)b * 128 + c] = a + __ldg(&bvc[c]);
}

// ---------------- phase 3: wmma fused chain (pipelined weight staging) ------
#define I_STR 264
#define H_STR 136
#define FO_STR 132
#define W_STR 136
#define RGN 34816
#define SM_FUSED_BYTES (3 * RGN + 2 * 16 * W_STR * 2)   // 113152

__global__ void __launch_bounds__(256, 2)
k_fused(const void* __restrict__ ids,
        const float* __restrict__ bg1, const float* __restrict__ bg2,
        const float* __restrict__ bp,  float* __restrict__ out, int n) {
    extern __shared__ unsigned char smraw[];
    __nv_bfloat16* ih  = (__nv_bfloat16*)(smraw);            // 64*264
    __nv_bfloat16* il  = (__nv_bfloat16*)(smraw + RGN);      // 64*264
    __nv_bfloat16* h1h = (__nv_bfloat16*)(smraw + 2 * RGN);  // 64*136
    __nv_bfloat16* h1l = h1h + 64 * H_STR;
    float*        outb = (float*)(smraw);                    // reuse RA
    __nv_bfloat16* tbh = (__nv_bfloat16*)(smraw + RGN);      // reuse RB
    __nv_bfloat16* tbl = tbh + 64 * H_STR;
    __nv_bfloat16* wsh = (__nv_bfloat16*)(smraw + 3 * RGN);  // 16*136
    __nv_bfloat16* wsl = wsh + 16 * W_STR;
    __shared__ int ids_s[64];

    const bool is64 = (g_or == 0u);
    const int tid = threadIdx.x;
    const int wid = tid >> 5;
    const int row0 = blockIdx.x * 64;
    const float scale = 0.17677669529663687f;   // (128/4)^-0.5
    const int wr = wid >> 1;
    const int wc = wid & 1;
    const int ep_r = tid >> 2;
    const int ep_c0 = (tid & 3) * 32;
    const int prow = tid >> 4;
    const int pcol = tid & 15;

    if (tid < 64) {
        int r = row0 + tid;
        ids_s[tid] = (r < n) ? get_id(ids, r, is64) : -1;
    }
    __syncthreads();

    // prefetch GEMM1 chunk 0 (overlaps stage-a)
    uint4 ph = ((const uint4*)g_wg1h)[prow * 16 + pcol];
    uint4 pl = ((const uint4*)g_wg1l)[prow * 16 + pcol];

    // stage a: inter = [q,q]*kctx*scale -> bf16 hi/lo
    for (int t = tid; t < 64 * 64; t += 256) {
        int r = t >> 6, c4 = t & 63;
        int b = ids_s[r];
        float4 iv = make_float4(0.f, 0.f, 0.f, 0.f);
        if (b >= 0) {
            float4 qv = ((const float4*)g_q)[(size_t)(row0 + r) * 32 + (c4 & 31)];
            float4 kc = ((const float4*)g_kc)[(size_t)b * 64 + c4];
            iv.x = qv.x * kc.x * scale; iv.y = qv.y * kc.y * scale;
            iv.z = qv.z * kc.z * scale; iv.w = qv.w * kc.w * scale;
        }
        float vv[4] = {iv.x, iv.y, iv.z, iv.w};
        #pragma unroll
        for (int j = 0; j < 4; j++) {
            __nv_bfloat16 h, l;
            bfsplit(vv[j], h, l);
            ih[r * I_STR + c4 * 4 + j] = h;
            il[r * I_STR + c4 * 4 + j] = l;
        }
    }
    __syncthreads();
    *(uint4*)&wsh[prow * W_STR + pcol * 8] = ph;
    *(uint4*)&wsl[prow * W_STR + pcol * 8] = pl;
    __syncthreads();

    wmma::fragment<wmma::accumulator, 16, 16, 16, float> acc[4];

    // ---- GEMM1: h1 = relu(inter @ Wg1 + bg1), K=256, 16 chunks ----
    #pragma unroll
    for (int j = 0; j < 4; j++) wmma::fill_fragment(acc[j], 0.0f);
    for (int t = 0; t < 16; t++) {
        int k0 = t * 16;
        if (t + 1 < 16) {
            ph = ((const uint4*)g_wg1h)[((t + 1) * 16 + prow) * 16 + pcol];
            pl = ((const uint4*)g_wg1l)[((t + 1) * 16 + prow) * 16 + pcol];
        }
        wmma::fragment<wmma::matrix_a, 16, 16, 16, __nv_bfloat16, wmma::row_major> ah, al;
        wmma::load_matrix_sync(ah, &ih[(wr * 16) * I_STR + k0], I_STR);
        wmma::load_matrix_sync(al, &il[(wr * 16) * I_STR + k0], I_STR);
        #pragma unroll
        for (int j = 0; j < 4; j++) {
            wmma::fragment<wmma::matrix_b, 16, 16, 16, __nv_bfloat16, wmma::row_major> bh, bl;
            wmma::load_matrix_sync(bh, &wsh[wc * 64 + j * 16], W_STR);
            wmma::load_matrix_sync(bl, &wsl[wc * 64 + j * 16], W_STR);
            wmma::mma_sync(acc[j], ah, bh, acc[j]);
            wmma::mma_sync(acc[j], ah, bl, acc[j]);
            wmma::mma_sync(acc[j], al, bh, acc[j]);
        }
        __syncthreads();
        if (t + 1 < 16) {
            *(uint4*)&wsh[prow * W_STR + pcol * 8] = ph;
            *(uint4*)&wsl[prow * W_STR + pcol * 8] = pl;
        }
        __syncthreads();
    }
    #pragma unroll
    for (int j = 0; j < 4; j++)
        wmma::store_matrix_sync(&outb[(wr * 16) * FO_STR + wc * 64 + j * 16],
                                acc[j], FO_STR, wmma::mem_row_major);
    __syncthreads();
    #pragma unroll 8
    for (int c = 0; c < 32; c++) {
        int cc = ep_c0 + c;
        float v = fmaxf(outb[ep_r * FO_STR + cc] + __ldg(&bg1[cc]), 0.0f);
        __nv_bfloat16 h, l;
        bfsplit(v, h, l);
        h1h[ep_r * H_STR + cc] = h;
        h1l[ep_r * H_STR + cc] = l;
    }

    // ---- GEMM2: gate = sigmoid(h1 @ Wg2 + bg2); tbuf = gate * vcomb ----
    ph = ((const uint4*)g_wg2h)[prow * 16 + pcol];
    pl = ((const uint4*)g_wg2l)[prow * 16 + pcol];
    __syncthreads();   // h1 writes + prior wbuf reads done
    *(uint4*)&wsh[prow * W_STR + pcol * 8] = ph;
    *(uint4*)&wsl[prow * W_STR + pcol * 8] = pl;
    __syncthreads();
    #pragma unroll
    for (int j = 0; j < 4; j++) wmma::fill_fragment(acc[j], 0.0f);
    for (int t = 0; t < 8; t++) {
        int k0 = t * 16;
        if (t + 1 < 8) {
            ph = ((const uint4*)g_wg2h)[((t + 1) * 16 + prow) * 16 + pcol];
            pl = ((const uint4*)g_wg2l)[((t + 1) * 16 + prow) * 16 + pcol];
        }
        wmma::fragment<wmma::matrix_a, 16, 16, 16, __nv_bfloat16, wmma::row_major> ah, al;
        wmma::load_matrix_sync(ah, &h1h[(wr * 16) * H_STR + k0], H_STR);
        wmma::load_matrix_sync(al, &h1l[(wr * 16) * H_STR + k0], H_STR);
        #pragma unroll
        for (int j = 0; j < 4; j++) {
            wmma::fragment<wmma::matrix_b, 16, 16, 16, __nv_bfloat16, wmma::row_major> bh, bl;
            wmma::load_matrix_sync(bh, &wsh[wc * 64 + j * 16], W_STR);
            wmma::load_matrix_sync(bl, &wsl[wc * 64 + j * 16], W_STR);
            wmma::mma_sync(acc[j], ah, bh, acc[j]);
            wmma::mma_sync(acc[j], ah, bl, acc[j]);
            wmma::mma_sync(acc[j], al, bh, acc[j]);
        }
        __syncthreads();
        if (t + 1 < 8) {
            *(uint4*)&wsh[prow * W_STR + pcol * 8] = ph;
            *(uint4*)&wsl[prow * W_STR + pcol * 8] = pl;
        }
        __syncthreads();
    }
    #pragma unroll
    for (int j = 0; j < 4; j++)
        wmma::store_matrix_sync(&outb[(wr * 16) * FO_STR + wc * 64 + j * 16],
                                acc[j], FO_STR, wmma::mem_row_major);
    __syncthreads();
    {
        int b = ids_s[ep_r];
        #pragma unroll 8
        for (int c = 0; c < 32; c++) {
            int cc = ep_c0 + c;
            float gate = 1.0f / (1.0f + __expf(-(outb[ep_r * FO_STR + cc] + __ldg(&bg2[cc]))));
            float vc = (b >= 0) ? g_vcomb[(size_t)b * 128 + cc] : 0.0f;
            __nv_bfloat16 h, l;
            bfsplit(gate * vc, h, l);
            tbh[ep_r * H_STR + cc] = h;
            tbl[ep_r * H_STR + cc] = l;
        }
    }

    // ---- GEMM3: out = tbuf @ Wp + bp ----
    ph = ((const uint4*)g_wph)[prow * 16 + pcol];
    pl = ((const uint4*)g_wpl)[prow * 16 + pcol];
    __syncthreads();   // tbuf writes + prior wbuf reads done
    *(uint4*)&wsh[prow * W_STR + pcol * 8] = ph;
    *(uint4*)&wsl[prow * W_STR + pcol * 8] = pl;
    __syncthreads();
    #pragma unroll
    for (int j = 0; j < 4; j++) wmma::fill_fragment(acc[j], 0.0f);
    for (int t = 0; t < 8; t++) {
        int k0 = t * 16;
        if (t + 1 < 8) {
            ph = ((const uint4*)g_wph)[((t + 1) * 16 + prow) * 16 + pcol];
            pl = ((const uint4*)g_wpl)[((t + 1) * 16 + prow) * 16 + pcol];
        }
        wmma::fragment<wmma::matrix_a, 16, 16, 16, __nv_bfloat16, wmma::row_major> ah, al;
        wmma::load_matrix_sync(ah, &tbh[(wr * 16) * H_STR + k0], H_STR);
        wmma::load_matrix_sync(al, &tbl[(wr * 16) * H_STR + k0], H_STR);
        #pragma unroll
        for (int j = 0; j < 4; j++) {
            wmma::fragment<wmma::matrix_b, 16, 16, 16, __nv_bfloat16, wmma::row_major> bh, bl;
            wmma::load_matrix_sync(bh, &wsh[wc * 64 + j * 16], W_STR);
            wmma::load_matrix_sync(bl, &wsl[wc * 64 + j * 16], W_STR);
            wmma::mma_sync(acc[j], ah, bh, acc[j]);
            wmma::mma_sync(acc[j], ah, bl, acc[j]);
            wmma::mma_sync(acc[j], al, bh, acc[j]);
        }
        __syncthreads();
        if (t + 1 < 8) {
            *(uint4*)&wsh[prow * W_STR + pcol * 8] = ph;
            *(uint4*)&wsl[prow * W_STR + pcol * 8] = pl;
        }
        __syncthreads();
    }
    #pragma unroll
    for (int j = 0; j < 4; j++)
        wmma::store_matrix_sync(&outb[(wr * 16) * FO_STR + wc * 64 + j * 16],
                                acc[j], FO_STR, wmma::mem_row_major);
    __syncthreads();
    {
        int grow = row0 + ep_r;
        if (grow < n) {
            float* op = &out[(size_t)grow * 128];
            #pragma unroll
            for (int c = 0; c < 32; c += 4) {
                int cc = ep_c0 + c;
                float4 o = *(const float4*)&outb[ep_r * FO_STR + cc];
                float4 b4 = *(const float4*)&bp[cc];
                *(float4*)&op[cc] = make_float4(o.x + b4.x, o.y + b4.y,
                                                o.z + b4.z, o.w + b4.w);
            }
        }
    }
}

// ---------------- launch ----------------------------------------------------
extern "C" void kernel_launch(void* const* d_in, const int* in_sizes, int n_in,
                              void* d_out, int out_size) {
    const float* x   = (const float*)d_in[0];
    const void*  ids = d_in[1];
    // d_in[2] = total_buckets (constant 8192, unused)
    const float *Wq = (const float*)d_in[3],  *bq = (const float*)d_in[4];
    const float *Wk = (const float*)d_in[5],  *bk = (const float*)d_in[6];
    const float *Wv = (const float*)d_in[7],  *bv = (const float*)d_in[8];
    const float *Wg1 = (const float*)d_in[9], *bg1 = (const float*)d_in[10];
    const float *Wg2 = (const float*)d_in[11], *bg2 = (const float*)d_in[12];
    const float *Wvc = (const float*)d_in[13], *bvc = (const float*)d_in[14];
    const float *Wp  = (const float*)d_in[15], *bp  = (const float*)d_in[16];
    float* out = (float*)d_out;

    const int n = in_sizes[0] / CC;

    static int smem_set = 0;
    if (!smem_set) {
        cudaFuncSetAttribute(k_qkv,   cudaFuncAttributeMaxDynamicSharedMemorySize, SM_QKV_BYTES);
        cudaFuncSetAttribute(k_fused, cudaFuncAttributeMaxDynamicSharedMemorySize, SM_FUSED_BYTES);
        smem_set = 1;
    }

    k_init<<<512, 256>>>();
    k_detect<<<256, 256>>>((const unsigned*)ids, in_sizes[1]);
    k_prep<<<448, 256>>>(Wq, Wk, Wv, Wg1, Wg2, Wp);

    int g1 = (n + 63) / 64;
    k_qkv<<<g1, 256, SM_QKV_BYTES>>>(x, ids, bq, bk, bv, n);

    k_cent<<<BKT / 2, 256>>>(Wk, bk, Wv, bv, Wvc, bvc);

    k_fused<<<g1, 256, SM_FUSED_BYTES>>>(ids, bg1, bg2, bp, out, n);
}

// round 14
// speedup vs baseline: 1.1930x; 1.0320x over previous
#include <cuda_runtime.h>
#include <cuda_bf16.h>
#include <mma.h>
#include <cstdint>

using namespace nvcuda;

#define CC   128
#define BKT  8192
#define NMAX 500000

// ---------------- scratch (__device__ globals; no allocs allowed) ----------
__device__ float    g_q[(size_t)(NMAX + 64) * CC];   // padded for edge-tile store
__device__ float    g_xsum[BKT * CC];
__device__ unsigned g_kkey[BKT * CC];
__device__ unsigned g_vkey[BKT * CC];
__device__ float    g_counts[BKT];
__device__ float    g_kc[BKT * 2 * CC];          // [k_mean | k_max] per bucket
__device__ float    g_vcomb[BKT * CC];           // [v_mean|v_max] @ Wvc + bvc
__device__ unsigned g_or;                        // 0 => ids are int64
// pre-split weights (bf16 hi/lo, row-major ldm=128)
__device__ __align__(256) __nv_bfloat16 g_wqh[128 * 128], g_wql[128 * 128];
__device__ __align__(256) __nv_bfloat16 g_wkh[128 * 128], g_wkl[128 * 128];
__device__ __align__(256) __nv_bfloat16 g_wvh[128 * 128], g_wvl[128 * 128];
__device__ __align__(256) __nv_bfloat16 g_wg1h[256 * 128], g_wg1l[256 * 128];
__device__ __align__(256) __nv_bfloat16 g_wg2h[128 * 128], g_wg2l[128 * 128];
__device__ __align__(256) __nv_bfloat16 g_wph[128 * 128],  g_wpl[128 * 128];
// bias tiles: 16 identical rows of each bias (bq,bk,bv,bg1,bg2,bp)
__device__ __align__(256) float g_btile[6][16 * 128];

// monotonic float<->uint mapping for atomicMax on floats
__device__ __forceinline__ unsigned fenc(float f) {
    unsigned u = __float_as_uint(f);
    return (u & 0x80000000u) ? ~u : (u | 0x80000000u);
}
__device__ __forceinline__ float fdec(unsigned e) {
    return (e & 0x80000000u) ? __uint_as_float(e ^ 0x80000000u)
                             : __uint_as_float(~e);
}
__device__ __forceinline__ int get_id(const void* ids, int i, bool is64) {
    return is64 ? (int)((const long long*)ids)[i] : ((const int*)ids)[i];
}
__device__ __forceinline__ void bfsplit(float v, __nv_bfloat16& h, __nv_bfloat16& l) {
    h = __float2bfloat16(v);
    l = __float2bfloat16(v - __bfloat162float(h));
}

// ---------------- init ------------------------------------------------------
__global__ void k_init() {
    size_t i = (size_t)blockIdx.x * blockDim.x + threadIdx.x;
    size_t stride = (size_t)gridDim.x * blockDim.x;
    for (size_t t = i; t < (size_t)BKT * CC; t += stride) {
        g_xsum[t] = 0.0f; g_kkey[t] = 0u; g_vkey[t] = 0u;
    }
    for (size_t t = i; t < BKT; t += stride) g_counts[t] = 0.0f;
    if (i == 0) g_or = 0u;
}

// ---------------- id dtype detection ---------------------------------------
__global__ void k_detect(const unsigned* __restrict__ w, int nwords) {
    unsigned acc = 0;
    int gid = blockIdx.x * blockDim.x + threadIdx.x;
    int stride = gridDim.x * blockDim.x;
    for (int t = 1 + 2 * gid; t < nwords; t += 2 * stride) acc |= w[t];
    for (int o = 16; o; o >>= 1) acc |= __shfl_xor_sync(0xFFFFFFFFu, acc, o);
    if ((threadIdx.x & 31) == 0 && acc) atomicOr(&g_or, acc);
}

// ---------------- weight prep: splits + bias tiles --------------------------
__global__ void k_prep(const float* __restrict__ Wq, const float* __restrict__ Wk,
                       const float* __restrict__ Wv, const float* __restrict__ Wg1,
                       const float* __restrict__ Wg2, const float* __restrict__ Wp,
                       const float* __restrict__ bq, const float* __restrict__ bk,
                       const float* __restrict__ bv, const float* __restrict__ bg1,
                       const float* __restrict__ bg2, const float* __restrict__ bp) {
    int t = blockIdx.x * 256 + threadIdx.x;     // 114688 weights + 12288 bias
    if (t >= 114688 + 12288) return;
    if (t >= 114688) {
        int t2 = t - 114688;
        int which = t2 >> 11, idx = t2 & 2047, c = idx & 127;
        const float* Bs[6] = {bq, bk, bv, bg1, bg2, bp};
        g_btile[which][idx] = Bs[which][c];
        return;
    }
    __nv_bfloat16 h, l;
    if (t < 16384) {
        bfsplit(Wq[t], h, l); g_wqh[t] = h; g_wql[t] = l;
    } else if (t < 32768) {
        int i = t - 16384;
        bfsplit(Wk[i], h, l); g_wkh[i] = h; g_wkl[i] = l;
    } else if (t < 49152) {
        int i = t - 32768;
        bfsplit(Wv[i], h, l); g_wvh[i] = h; g_wvl[i] = l;
    } else if (t < 81920) {
        int i = t - 49152;
        bfsplit(Wg1[i], h, l); g_wg1h[i] = h; g_wg1l[i] = l;
    } else if (t < 98304) {
        int i = t - 81920;
        bfsplit(Wg2[i], h, l); g_wg2h[i] = h; g_wg2l[i] = l;
    } else {
        int i = t - 98304;
        bfsplit(Wp[i], h, l);  g_wph[i] = h;  g_wpl[i] = l;
    }
}

// ---------------- phase 1: wmma qkv (double-buffered, bias-init, direct q) --
#define QX_STR 136
#define QW_STR 136
#define QO_STR 132
#define WBUF_ELEMS (2 * 16 * QW_STR)   // one buffer: hi+lo
#define SM_QKV_BYTES ((2 * 64 * QX_STR + 2 * WBUF_ELEMS) * 2 + 64 * QO_STR * 4) // 86016

__global__ void __launch_bounds__(256, 2)
k_qkv(const float* __restrict__ x, const void* __restrict__ ids, int n) {
    extern __shared__ unsigned char smraw[];
    __nv_bfloat16* xs_hi = (__nv_bfloat16*)smraw;                  // 64*136
    __nv_bfloat16* xs_lo = xs_hi + 64 * QX_STR;
    __nv_bfloat16* wbuf  = xs_lo + 64 * QX_STR;                    // 2 buffers
    float*         outb  = (float*)(wbuf + 2 * WBUF_ELEMS);        // 64*132
    __shared__ int ids_s[64];

    const bool is64 = (g_or == 0u);
    const int tid = threadIdx.x;
    const int wid = tid >> 5;
    const int row0 = blockIdx.x * 64;
    const int wr = wid >> 1;            // rows wr*16
    const int wc = wid & 1;             // cols wc*64
    const int ep_r = tid >> 2;          // 0..63
    const int ep_c0 = (tid & 3) * 32;   // 32 cols
    const int prow = tid >> 4;          // staging row 0..15
    const int pcol = tid & 15;          // staging uint4 col

    const __nv_bfloat16* WHs[3] = {g_wqh, g_wkh, g_wvh};
    const __nv_bfloat16* WLs[3] = {g_wql, g_wkl, g_wvl};

    if (tid < 64) {
        int r = row0 + tid;
        ids_s[tid] = (r < n) ? get_id(ids, r, is64) : -1;
    }

    // prefetch chunk 0 (overlaps x conversion)
    uint4 ph = ((const uint4*)WHs[0])[prow * 16 + pcol];
    uint4 pl = ((const uint4*)WLs[0])[prow * 16 + pcol];

    // x tile -> bf16 hi/lo
    for (int t = tid; t < 64 * 32; t += 256) {
        int r = t >> 5, c4 = t & 31;
        float4 v = make_float4(0.f, 0.f, 0.f, 0.f);
        if (row0 + r < n) v = ((const float4*)x)[(size_t)(row0 + r) * 32 + c4];
        float vv[4] = {v.x, v.y, v.z, v.w};
        #pragma unroll
        for (int j = 0; j < 4; j++) {
            __nv_bfloat16 h, l;
            bfsplit(vv[j], h, l);
            xs_hi[r * QX_STR + c4 * 4 + j] = h;
            xs_lo[r * QX_STR + c4 * 4 + j] = l;
        }
    }
    // store chunk 0 into buf 0; prefetch chunk 1
    *(uint4*)&wbuf[prow * QW_STR + pcol * 8] = ph;
    *(uint4*)&wbuf[16 * QW_STR + prow * QW_STR + pcol * 8] = pl;
    ph = ((const uint4*)WHs[0])[(16 + prow) * 16 + pcol];
    pl = ((const uint4*)WLs[0])[(16 + prow) * 16 + pcol];
    __syncthreads();

    wmma::fragment<wmma::accumulator, 16, 16, 16, float> acc[4];

    for (int t = 0; t < 24; t++) {
        const int mm = t >> 3, ks = t & 7, k0 = ks * 16;
        const int cur = t & 1;
        __nv_bfloat16* cwh = wbuf + cur * WBUF_ELEMS;
        __nv_bfloat16* cwl = cwh + 16 * QW_STR;
        __nv_bfloat16* nwh = wbuf + (1 - cur) * WBUF_ELEMS;
        __nv_bfloat16* nwl = nwh + 16 * QW_STR;

        if (ks == 0) {   // bias-initialized accumulators
            #pragma unroll
            for (int j = 0; j < 4; j++)
                wmma::load_matrix_sync(acc[j], &g_btile[mm][wc * 64 + j * 16],
                                       128, wmma::mem_row_major);
        }
        if (t + 1 < 24) {   // store prefetched chunk t+1 into the other buffer
            *(uint4*)&nwh[prow * QW_STR + pcol * 8] = ph;
            *(uint4*)&nwl[prow * QW_STR + pcol * 8] = pl;
        }
        if (t + 2 < 24) {   // prefetch chunk t+2
            int m2 = (t + 2) >> 3, k2 = ((t + 2) & 7) * 16;
            ph = ((const uint4*)WHs[m2])[(k2 + prow) * 16 + pcol];
            pl = ((const uint4*)WLs[m2])[(k2 + prow) * 16 + pcol];
        }
        {
            wmma::fragment<wmma::matrix_a, 16, 16, 16, __nv_bfloat16, wmma::row_major> ah, al;
            wmma::load_matrix_sync(ah, &xs_hi[(wr * 16) * QX_STR + k0], QX_STR);
            wmma::load_matrix_sync(al, &xs_lo[(wr * 16) * QX_STR + k0], QX_STR);
            #pragma unroll
            for (int j = 0; j < 4; j++) {
                wmma::fragment<wmma::matrix_b, 16, 16, 16, __nv_bfloat16, wmma::row_major> bh, bl;
                wmma::load_matrix_sync(bh, &cwh[wc * 64 + j * 16], QW_STR);
                wmma::load_matrix_sync(bl, &cwl[wc * 64 + j * 16], QW_STR);
                wmma::mma_sync(acc[j], ah, bh, acc[j]);
                wmma::mma_sync(acc[j], ah, bl, acc[j]);
                wmma::mma_sync(acc[j], al, bh, acc[j]);
            }
        }
        if (ks == 7) {
            if (mm == 0) {   // q: direct global store (bias already inside)
                #pragma unroll
                for (int j = 0; j < 4; j++)
                    wmma::store_matrix_sync(
                        &g_q[(size_t)(row0 + wr * 16) * 128 + wc * 64 + j * 16],
                        acc[j], 128, wmma::mem_row_major);
            } else {
                #pragma unroll
                for (int j = 0; j < 4; j++)
                    wmma::store_matrix_sync(&outb[(wr * 16) * QO_STR + wc * 64 + j * 16],
                                            acc[j], QO_STR, wmma::mem_row_major);
            }
        }
        __syncthreads();   // next-buffer stores + outb visible

        if (ks == 7 && mm > 0) {
            int b = ids_s[ep_r];
            if (b >= 0) {
                unsigned* p = ((mm == 1) ? g_kkey : g_vkey) + (size_t)b * 128;
                #pragma unroll 8
                for (int c = 0; c < 32; c++) {
                    int cc = ep_c0 + c;
                    atomicMax(&p[cc], fenc(outb[ep_r * QO_STR + cc]));
                }
            }
        }
    }

    // x_sum + counts (xs never overwritten)
    {
        int b = ids_s[ep_r];
        if (b >= 0) {
            float* dst = &g_xsum[(size_t)b * 128];
            #pragma unroll 8
            for (int c = 0; c < 32; c++) {
                int cc = ep_c0 + c;
                float v = __bfloat162float(xs_hi[ep_r * QX_STR + cc])
                        + __bfloat162float(xs_lo[ep_r * QX_STR + cc]);
                atomicAdd(&dst[cc], v);
            }
            if ((tid & 3) == 0) atomicAdd(&g_counts[b], 1.0f);
        }
    }
}

// ---------------- phase 2: centroid finalize + per-bucket Wvc GEMM ----------
__global__ void __launch_bounds__(256)
k_cent(const float* __restrict__ Wk,  const float* __restrict__ bk,
       const float* __restrict__ Wv,  const float* __restrict__ bv,
       const float* __restrict__ Wvc, const float* __restrict__ bvc) {
    __shared__ float vt[2][256];
    int tid = threadIdx.x;
    int bl = tid >> 7, c = tid & 127;
    int b = blockIdx.x * 2 + bl;

    float cnt = g_counts[b];
    float inv = 1.0f / fmaxf(cnt, 1.0f);
    const float* xs = &g_xsum[(size_t)b * 128];
    float ak = 0.0f, av = 0.0f;
    #pragma unroll 4
    for (int k = 0; k < 128; k++) {
        float xv = xs[k];
        ak = fmaf(xv, __ldg(&Wk[k * 128 + c]), ak);
        av = fmaf(xv, __ldg(&Wv[k * 128 + c]), av);
    }
    float kmean = (ak + cnt * __ldg(&bk[c])) * inv;
    float vmean = (av + cnt * __ldg(&bv[c])) * inv;
    bool ne = cnt > 0.0f;
    float kmax = ne ? fdec(g_kkey[(size_t)b * 128 + c]) : 0.0f;
    float vmax = ne ? fdec(g_vkey[(size_t)b * 128 + c]) : 0.0f;

    g_kc[(size_t)b * 256 + c]       = kmean;
    g_kc[(size_t)b * 256 + 128 + c] = kmax;
    vt[bl][c]       = vmean;
    vt[bl][128 + c] = vmax;
    __syncthreads();

    float a = 0.0f;
    #pragma unroll 4
    for (int k = 0; k < 256; k++)
        a = fmaf(vt[bl][k], __ldg(&Wvc[k * 128 + c]), a);
    g_vcomb[(size_t)b * 128 + c] = a + __ldg(&bvc[c]);
}

// ---------------- phase 3: wmma fused chain (bias-init, direct out store) ---
#define I_STR 264
#define H_STR 136
#define FO_STR 132
#define W_STR 136
#define RGN 34816
#define SM_FUSED_BYTES (3 * RGN + 2 * 16 * W_STR * 2)   // 113152

__global__ void __launch_bounds__(256, 2)
k_fused(const void* __restrict__ ids, float* __restrict__ out, int n) {
    extern __shared__ unsigned char smraw[];
    __nv_bfloat16* ih  = (__nv_bfloat16*)(smraw);            // 64*264
    __nv_bfloat16* il  = (__nv_bfloat16*)(smraw + RGN);      // 64*264
    __nv_bfloat16* h1h = (__nv_bfloat16*)(smraw + 2 * RGN);  // 64*136
    __nv_bfloat16* h1l = h1h + 64 * H_STR;
    float*        outb = (float*)(smraw);                    // reuse RA
    __nv_bfloat16* tbh = (__nv_bfloat16*)(smraw + RGN);      // reuse RB
    __nv_bfloat16* tbl = tbh + 64 * H_STR;
    __nv_bfloat16* wsh = (__nv_bfloat16*)(smraw + 3 * RGN);  // 16*136
    __nv_bfloat16* wsl = wsh + 16 * W_STR;
    __shared__ int ids_s[64];

    const bool is64 = (g_or == 0u);
    const int tid = threadIdx.x;
    const int wid = tid >> 5;
    const int row0 = blockIdx.x * 64;
    const float scale = 0.17677669529663687f;   // (128/4)^-0.5
    const int wr = wid >> 1;
    const int wc = wid & 1;
    const int ep_r = tid >> 2;
    const int ep_c0 = (tid & 3) * 32;
    const int prow = tid >> 4;
    const int pcol = tid & 15;
    const bool full = (row0 + 64 <= n);

    if (tid < 64) {
        int r = row0 + tid;
        ids_s[tid] = (r < n) ? get_id(ids, r, is64) : -1;
    }
    __syncthreads();

    // prefetch GEMM1 chunk 0 (overlaps stage-a)
    uint4 ph = ((const uint4*)g_wg1h)[prow * 16 + pcol];
    uint4 pl = ((const uint4*)g_wg1l)[prow * 16 + pcol];

    // stage a: inter = [q,q]*kctx*scale -> bf16 hi/lo  (q already has bias)
    for (int t = tid; t < 64 * 64; t += 256) {
        int r = t >> 6, c4 = t & 63;
        int b = ids_s[r];
        float4 iv = make_float4(0.f, 0.f, 0.f, 0.f);
        if (b >= 0) {
            float4 qv = ((const float4*)g_q)[(size_t)(row0 + r) * 32 + (c4 & 31)];
            float4 kc = ((const float4*)g_kc)[(size_t)b * 64 + c4];
            iv.x = qv.x * kc.x * scale; iv.y = qv.y * kc.y * scale;
            iv.z = qv.z * kc.z * scale; iv.w = qv.w * kc.w * scale;
        }
        float vv[4] = {iv.x, iv.y, iv.z, iv.w};
        #pragma unroll
        for (int j = 0; j < 4; j++) {
            __nv_bfloat16 h, l;
            bfsplit(vv[j], h, l);
            ih[r * I_STR + c4 * 4 + j] = h;
            il[r * I_STR + c4 * 4 + j] = l;
        }
    }
    __syncthreads();
    *(uint4*)&wsh[prow * W_STR + pcol * 8] = ph;
    *(uint4*)&wsl[prow * W_STR + pcol * 8] = pl;
    __syncthreads();

    wmma::fragment<wmma::accumulator, 16, 16, 16, float> acc[4];

    // ---- GEMM1: h1 = relu(inter @ Wg1 + bg1), K=256, 16 chunks ----
    #pragma unroll
    for (int j = 0; j < 4; j++)
        wmma::load_matrix_sync(acc[j], &g_btile[3][wc * 64 + j * 16], 128, wmma::mem_row_major);
    for (int t = 0; t < 16; t++) {
        int k0 = t * 16;
        if (t + 1 < 16) {
            ph = ((const uint4*)g_wg1h)[((t + 1) * 16 + prow) * 16 + pcol];
            pl = ((const uint4*)g_wg1l)[((t + 1) * 16 + prow) * 16 + pcol];
        }
        wmma::fragment<wmma::matrix_a, 16, 16, 16, __nv_bfloat16, wmma::row_major> ah, al;
        wmma::load_matrix_sync(ah, &ih[(wr * 16) * I_STR + k0], I_STR);
        wmma::load_matrix_sync(al, &il[(wr * 16) * I_STR + k0], I_STR);
        #pragma unroll
        for (int j = 0; j < 4; j++) {
            wmma::fragment<wmma::matrix_b, 16, 16, 16, __nv_bfloat16, wmma::row_major> bh, bl;
            wmma::load_matrix_sync(bh, &wsh[wc * 64 + j * 16], W_STR);
            wmma::load_matrix_sync(bl, &wsl[wc * 64 + j * 16], W_STR);
            wmma::mma_sync(acc[j], ah, bh, acc[j]);
            wmma::mma_sync(acc[j], ah, bl, acc[j]);
            wmma::mma_sync(acc[j], al, bh, acc[j]);
        }
        __syncthreads();
        if (t + 1 < 16) {
            *(uint4*)&wsh[prow * W_STR + pcol * 8] = ph;
            *(uint4*)&wsl[prow * W_STR + pcol * 8] = pl;
        }
        __syncthreads();
    }
    #pragma unroll
    for (int j = 0; j < 4; j++)
        wmma::store_matrix_sync(&outb[(wr * 16) * FO_STR + wc * 64 + j * 16],
                                acc[j], FO_STR, wmma::mem_row_major);
    __syncthreads();
    #pragma unroll 8
    for (int c = 0; c < 32; c++) {
        int cc = ep_c0 + c;
        float v = fmaxf(outb[ep_r * FO_STR + cc], 0.0f);   // bias already inside
        __nv_bfloat16 h, l;
        bfsplit(v, h, l);
        h1h[ep_r * H_STR + cc] = h;
        h1l[ep_r * H_STR + cc] = l;
    }

    // ---- GEMM2: gate = sigmoid(h1 @ Wg2 + bg2); tbuf = gate * vcomb ----
    ph = ((const uint4*)g_wg2h)[prow * 16 + pcol];
    pl = ((const uint4*)g_wg2l)[prow * 16 + pcol];
    __syncthreads();   // h1 writes + prior wbuf reads done
    *(uint4*)&wsh[prow * W_STR + pcol * 8] = ph;
    *(uint4*)&wsl[prow * W_STR + pcol * 8] = pl;
    __syncthreads();
    #pragma unroll
    for (int j = 0; j < 4; j++)
        wmma::load_matrix_sync(acc[j], &g_btile[4][wc * 64 + j * 16], 128, wmma::mem_row_major);
    for (int t = 0; t < 8; t++) {
        int k0 = t * 16;
        if (t + 1 < 8) {
            ph = ((const uint4*)g_wg2h)[((t + 1) * 16 + prow) * 16 + pcol];
            pl = ((const uint4*)g_wg2l)[((t + 1) * 16 + prow) * 16 + pcol];
        }
        wmma::fragment<wmma::matrix_a, 16, 16, 16, __nv_bfloat16, wmma::row_major> ah, al;
        wmma::load_matrix_sync(ah, &h1h[(wr * 16) * H_STR + k0], H_STR);
        wmma::load_matrix_sync(al, &h1l[(wr * 16) * H_STR + k0], H_STR);
        #pragma unroll
        for (int j = 0; j < 4; j++) {
            wmma::fragment<wmma::matrix_b, 16, 16, 16, __nv_bfloat16, wmma::row_major> bh, bl;
            wmma::load_matrix_sync(bh, &wsh[wc * 64 + j * 16], W_STR);
            wmma::load_matrix_sync(bl, &wsl[wc * 64 + j * 16], W_STR);
            wmma::mma_sync(acc[j], ah, bh, acc[j]);
            wmma::mma_sync(acc[j], ah, bl, acc[j]);
            wmma::mma_sync(acc[j], al, bh, acc[j]);
        }
        __syncthreads();
        if (t + 1 < 8) {
            *(uint4*)&wsh[prow * W_STR + pcol * 8] = ph;
            *(uint4*)&wsl[prow * W_STR + pcol * 8] = pl;
        }
        __syncthreads();
    }
    #pragma unroll
    for (int j = 0; j < 4; j++)
        wmma::store_matrix_sync(&outb[(wr * 16) * FO_STR + wc * 64 + j * 16],
                                acc[j], FO_STR, wmma::mem_row_major);
    __syncthreads();
    {
        int b = ids_s[ep_r];
        #pragma unroll 8
        for (int c = 0; c < 32; c++) {
            int cc = ep_c0 + c;
            float gate = 1.0f / (1.0f + __expf(-outb[ep_r * FO_STR + cc]));  // bias inside
            float vc = (b >= 0) ? g_vcomb[(size_t)b * 128 + cc] : 0.0f;
            __nv_bfloat16 h, l;
            bfsplit(gate * vc, h, l);
            tbh[ep_r * H_STR + cc] = h;
            tbl[ep_r * H_STR + cc] = l;
        }
    }

    // ---- GEMM3: out = tbuf @ Wp + bp ----
    ph = ((const uint4*)g_wph)[prow * 16 + pcol];
    pl = ((const uint4*)g_wpl)[prow * 16 + pcol];
    __syncthreads();   // tbuf writes + prior wbuf reads done
    *(uint4*)&wsh[prow * W_STR + pcol * 8] = ph;
    *(uint4*)&wsl[prow * W_STR + pcol * 8] = pl;
    __syncthreads();
    #pragma unroll
    for (int j = 0; j < 4; j++)
        wmma::load_matrix_sync(acc[j], &g_btile[5][wc * 64 + j * 16], 128, wmma::mem_row_major);
    for (int t = 0; t < 8; t++) {
        int k0 = t * 16;
        if (t + 1 < 8) {
            ph = ((const uint4*)g_wph)[((t + 1) * 16 + prow) * 16 + pcol];
            pl = ((const uint4*)g_wpl)[((t + 1) * 16 + prow) * 16 + pcol];
        }
        wmma::fragment<wmma::matrix_a, 16, 16, 16, __nv_bfloat16, wmma::row_major> ah, al;
        wmma::load_matrix_sync(ah, &tbh[(wr * 16) * H_STR + k0], H_STR);
        wmma::load_matrix_sync(al, &tbl[(wr * 16) * H_STR + k0], H_STR);
        #pragma unroll
        for (int j = 0; j < 4; j++) {
            wmma::fragment<wmma::matrix_b, 16, 16, 16, __nv_bfloat16, wmma::row_major> bh, bl;
            wmma::load_matrix_sync(bh, &wsh[wc * 64 + j * 16], W_STR);
            wmma::load_matrix_sync(bl, &wsl[wc * 64 + j * 16], W_STR);
            wmma::mma_sync(acc[j], ah, bh, acc[j]);
            wmma::mma_sync(acc[j], ah, bl, acc[j]);
            wmma::mma_sync(acc[j], al, bh, acc[j]);
        }
        __syncthreads();
        if (t + 1 < 8) {
            *(uint4*)&wsh[prow * W_STR + pcol * 8] = ph;
            *(uint4*)&wsl[prow * W_STR + pcol * 8] = pl;
        }
        __syncthreads();
    }
    if (full) {
        // direct global store (bias already inside accumulators)
        #pragma unroll
        for (int j = 0; j < 4; j++)
            wmma::store_matrix_sync(&out[(size_t)(row0 + wr * 16) * 128 + wc * 64 + j * 16],
                                    acc[j], 128, wmma::mem_row_major);
    } else {
        #pragma unroll
        for (int j = 0; j < 4; j++)
            wmma::store_matrix_sync(&outb[(wr * 16) * FO_STR + wc * 64 + j * 16],
                                    acc[j], FO_STR, wmma::mem_row_major);
        __syncthreads();
        int grow = row0 + ep_r;
        if (grow < n) {
            float* op = &out[(size_t)grow * 128];
            #pragma unroll
            for (int c = 0; c < 32; c += 4) {
                int cc = ep_c0 + c;
                float4 o = *(const float4*)&outb[ep_r * FO_STR + cc];
                *(float4*)&op[cc] = o;
            }
        }
    }
}

// ---------------- launch ----------------------------------------------------
extern "C" void kernel_launch(void* const* d_in, const int* in_sizes, int n_in,
                              void* d_out, int out_size) {
    const float* x   = (const float*)d_in[0];
    const void*  ids = d_in[1];
    // d_in[2] = total_buckets (constant 8192, unused)
    const float *Wq = (const float*)d_in[3],  *bq = (const float*)d_in[4];
    const float *Wk = (const float*)d_in[5],  *bk = (const float*)d_in[6];
    const float *Wv = (const float*)d_in[7],  *bv = (const float*)d_in[8];
    const float *Wg1 = (const float*)d_in[9], *bg1 = (const float*)d_in[10];
    const float *Wg2 = (const float*)d_in[11], *bg2 = (const float*)d_in[12];
    const float *Wvc = (const float*)d_in[13], *bvc = (const float*)d_in[14];
    const float *Wp  = (const float*)d_in[15], *bp  = (const float*)d_in[16];
    float* out = (float*)d_out;

    const int n = in_sizes[0] / CC;

    static int smem_set = 0;
    if (!smem_set) {
        cudaFuncSetAttribute(k_qkv,   cudaFuncAttributeMaxDynamicSharedMemorySize, SM_QKV_BYTES);
        cudaFuncSetAttribute(k_fused, cudaFuncAttributeMaxDynamicSharedMemorySize, SM_FUSED_BYTES);
        smem_set = 1;
    }

    k_init<<<512, 256>>>();
    k_detect<<<256, 256>>>((const unsigned*)ids, in_sizes[1]);
    k_prep<<<496, 256>>>(Wq, Wk, Wv, Wg1, Wg2, Wp, bq, bk, bv, bg1, bg2, bp);

    int g1 = (n + 63) / 64;
    k_qkv<<<g1, 256, SM_QKV_BYTES>>>(x, ids, n);

    k_cent<<<BKT / 2, 256>>>(Wk, bk, Wv, bv, Wvc, bvc);

    k_fused<<<g1, 256, SM_FUSED_BYTES>>>(ids, out, n);
}

// round 15
// speedup vs baseline: 1.3144x; 1.1017x over previous
#include <cuda_runtime.h>
#include <cuda_bf16.h>
#include <mma.h>
#include <cstdint>

using namespace nvcuda;

#define CC   128
#define BKT  8192
#define NMAX 500000

// ---------------- scratch (__device__ globals; no allocs allowed) ----------
__device__ float    g_q[(size_t)(NMAX + 64) * CC];   // padded for edge-tile store
__device__ float    g_xsum[BKT * CC];
__device__ unsigned g_kkey[BKT * CC];
__device__ unsigned g_vkey[BKT * CC];
__device__ float    g_counts[BKT];
__device__ float    g_kc[BKT * 2 * CC];          // [k_mean | k_max] per bucket
__device__ float    g_vcomb[BKT * CC];           // [v_mean|v_max] @ Wvc + bvc
__device__ unsigned g_or;                        // 0 => ids are int64
// pre-split weights (bf16 hi/lo, row-major ldm=128)
__device__ __align__(256) __nv_bfloat16 g_wqh[128 * 128], g_wql[128 * 128];
__device__ __align__(256) __nv_bfloat16 g_wkh[128 * 128], g_wkl[128 * 128];
__device__ __align__(256) __nv_bfloat16 g_wvh[128 * 128], g_wvl[128 * 128];
__device__ __align__(256) __nv_bfloat16 g_wg1h[256 * 128], g_wg1l[256 * 128];
__device__ __align__(256) __nv_bfloat16 g_wg2h[128 * 128], g_wg2l[128 * 128];
__device__ __align__(256) __nv_bfloat16 g_wph[128 * 128],  g_wpl[128 * 128];
// bias tiles: 16 identical rows of each bias (bq,bk,bv,bg1,bg2,bp)
__device__ __align__(256) float g_btile[6][16 * 128];

// monotonic float<->uint mapping for atomicMax on floats
__device__ __forceinline__ unsigned fenc(float f) {
    unsigned u = __float_as_uint(f);
    return (u & 0x80000000u) ? ~u : (u | 0x80000000u);
}
__device__ __forceinline__ float fdec(unsigned e) {
    return (e & 0x80000000u) ? __uint_as_float(e ^ 0x80000000u)
                             : __uint_as_float(~e);
}
__device__ __forceinline__ int get_id(const void* ids, int i, bool is64) {
    return is64 ? (int)((const long long*)ids)[i] : ((const int*)ids)[i];
}
__device__ __forceinline__ void bfsplit(float v, __nv_bfloat16& h, __nv_bfloat16& l) {
    h = __float2bfloat16(v);
    l = __float2bfloat16(v - __bfloat162float(h));
}

// ---------------- init ------------------------------------------------------
__global__ void k_init() {
    size_t i = (size_t)blockIdx.x * blockDim.x + threadIdx.x;
    size_t stride = (size_t)gridDim.x * blockDim.x;
    for (size_t t = i; t < (size_t)BKT * CC; t += stride) {
        g_xsum[t] = 0.0f; g_kkey[t] = 0u; g_vkey[t] = 0u;
    }
    for (size_t t = i; t < BKT; t += stride) g_counts[t] = 0.0f;
    if (i == 0) g_or = 0u;
}

// ---------------- id dtype detection ---------------------------------------
__global__ void k_detect(const unsigned* __restrict__ w, int nwords) {
    unsigned acc = 0;
    int gid = blockIdx.x * blockDim.x + threadIdx.x;
    int stride = gridDim.x * blockDim.x;
    for (int t = 1 + 2 * gid; t < nwords; t += 2 * stride) acc |= w[t];
    for (int o = 16; o; o >>= 1) acc |= __shfl_xor_sync(0xFFFFFFFFu, acc, o);
    if ((threadIdx.x & 31) == 0 && acc) atomicOr(&g_or, acc);
}

// ---------------- weight prep: splits + bias tiles --------------------------
__global__ void k_prep(const float* __restrict__ Wq, const float* __restrict__ Wk,
                       const float* __restrict__ Wv, const float* __restrict__ Wg1,
                       const float* __restrict__ Wg2, const float* __restrict__ Wp,
                       const float* __restrict__ bq, const float* __restrict__ bk,
                       const float* __restrict__ bv, const float* __restrict__ bg1,
                       const float* __restrict__ bg2, const float* __restrict__ bp) {
    int t = blockIdx.x * 256 + threadIdx.x;     // 114688 weights + 12288 bias
    if (t >= 114688 + 12288) return;
    if (t >= 114688) {
        int t2 = t - 114688;
        int which = t2 >> 11, idx = t2 & 2047, c = idx & 127;
        const float* Bs[6] = {bq, bk, bv, bg1, bg2, bp};
        g_btile[which][idx] = Bs[which][c];
        return;
    }
    __nv_bfloat16 h, l;
    if (t < 16384) {
        bfsplit(Wq[t], h, l); g_wqh[t] = h; g_wql[t] = l;
    } else if (t < 32768) {
        int i = t - 16384;
        bfsplit(Wk[i], h, l); g_wkh[i] = h; g_wkl[i] = l;
    } else if (t < 49152) {
        int i = t - 32768;
        bfsplit(Wv[i], h, l); g_wvh[i] = h; g_wvl[i] = l;
    } else if (t < 81920) {
        int i = t - 49152;
        bfsplit(Wg1[i], h, l); g_wg1h[i] = h; g_wg1l[i] = l;
    } else if (t < 98304) {
        int i = t - 81920;
        bfsplit(Wg2[i], h, l); g_wg2h[i] = h; g_wg2l[i] = l;
    } else {
        int i = t - 98304;
        bfsplit(Wp[i], h, l);  g_wph[i] = h;  g_wpl[i] = l;
    }
}

// ---------------- phase 1: wmma qkv (32x32 warp tiles, double-buffered) -----
#define QX_STR 136
#define QW_STR 136
#define QO_STR 132
#define WBUF_ELEMS (2 * 16 * QW_STR)   // one buffer: hi+lo
#define SM_QKV_BYTES ((2 * 64 * QX_STR + 2 * WBUF_ELEMS) * 2 + 64 * QO_STR * 4) // 86016

__global__ void __launch_bounds__(256, 2)
k_qkv(const float* __restrict__ x, const void* __restrict__ ids, int n) {
    extern __shared__ unsigned char smraw[];
    __nv_bfloat16* xs_hi = (__nv_bfloat16*)smraw;                  // 64*136
    __nv_bfloat16* xs_lo = xs_hi + 64 * QX_STR;
    __nv_bfloat16* wbuf  = xs_lo + 64 * QX_STR;                    // 2 buffers
    float*         outb  = (float*)(wbuf + 2 * WBUF_ELEMS);        // 64*132
    __shared__ int ids_s[64];

    const bool is64 = (g_or == 0u);
    const int tid = threadIdx.x;
    const int wid = tid >> 5;
    const int row0 = blockIdx.x * 64;
    const int wr = wid >> 2;            // 0..1 : rows wr*32
    const int wc = wid & 3;             // 0..3 : cols wc*32
    const int ep_r = tid >> 2;          // 0..63
    const int ep_c0 = (tid & 3) * 32;   // 32 cols
    const int prow = tid >> 4;          // staging row 0..15
    const int pcol = tid & 15;          // staging uint4 col

    const __nv_bfloat16* WHs[3] = {g_wqh, g_wkh, g_wvh};
    const __nv_bfloat16* WLs[3] = {g_wql, g_wkl, g_wvl};

    if (tid < 64) {
        int r = row0 + tid;
        ids_s[tid] = (r < n) ? get_id(ids, r, is64) : -1;
    }

    // prefetch chunk 0 (overlaps x conversion)
    uint4 ph = ((const uint4*)WHs[0])[prow * 16 + pcol];
    uint4 pl = ((const uint4*)WLs[0])[prow * 16 + pcol];

    // x tile -> bf16 hi/lo
    for (int t = tid; t < 64 * 32; t += 256) {
        int r = t >> 5, c4 = t & 31;
        float4 v = make_float4(0.f, 0.f, 0.f, 0.f);
        if (row0 + r < n) v = ((const float4*)x)[(size_t)(row0 + r) * 32 + c4];
        float vv[4] = {v.x, v.y, v.z, v.w};
        #pragma unroll
        for (int j = 0; j < 4; j++) {
            __nv_bfloat16 h, l;
            bfsplit(vv[j], h, l);
            xs_hi[r * QX_STR + c4 * 4 + j] = h;
            xs_lo[r * QX_STR + c4 * 4 + j] = l;
        }
    }
    // store chunk 0 into buf 0; prefetch chunk 1
    *(uint4*)&wbuf[prow * QW_STR + pcol * 8] = ph;
    *(uint4*)&wbuf[16 * QW_STR + prow * QW_STR + pcol * 8] = pl;
    ph = ((const uint4*)WHs[0])[(16 + prow) * 16 + pcol];
    pl = ((const uint4*)WLs[0])[(16 + prow) * 16 + pcol];
    __syncthreads();

    wmma::fragment<wmma::accumulator, 16, 16, 16, float> acc[2][2];

    for (int t = 0; t < 24; t++) {
        const int mm = t >> 3, ks = t & 7, k0 = ks * 16;
        const int cur = t & 1;
        __nv_bfloat16* cwh = wbuf + cur * WBUF_ELEMS;
        __nv_bfloat16* cwl = cwh + 16 * QW_STR;
        __nv_bfloat16* nwh = wbuf + (1 - cur) * WBUF_ELEMS;
        __nv_bfloat16* nwl = nwh + 16 * QW_STR;

        if (ks == 0) {   // bias-initialized accumulators
            #pragma unroll
            for (int i = 0; i < 2; i++)
                #pragma unroll
                for (int j = 0; j < 2; j++)
                    wmma::load_matrix_sync(acc[i][j], &g_btile[mm][wc * 32 + j * 16],
                                           128, wmma::mem_row_major);
        }
        if (t + 1 < 24) {   // store prefetched chunk t+1 into the other buffer
            *(uint4*)&nwh[prow * QW_STR + pcol * 8] = ph;
            *(uint4*)&nwl[prow * QW_STR + pcol * 8] = pl;
        }
        if (t + 2 < 24) {   // prefetch chunk t+2
            int m2 = (t + 2) >> 3, k2 = ((t + 2) & 7) * 16;
            ph = ((const uint4*)WHs[m2])[(k2 + prow) * 16 + pcol];
            pl = ((const uint4*)WLs[m2])[(k2 + prow) * 16 + pcol];
        }
        {
            wmma::fragment<wmma::matrix_a, 16, 16, 16, __nv_bfloat16, wmma::row_major> ah[2], al[2];
            #pragma unroll
            for (int i = 0; i < 2; i++) {
                wmma::load_matrix_sync(ah[i], &xs_hi[(wr * 32 + i * 16) * QX_STR + k0], QX_STR);
                wmma::load_matrix_sync(al[i], &xs_lo[(wr * 32 + i * 16) * QX_STR + k0], QX_STR);
            }
            #pragma unroll
            for (int j = 0; j < 2; j++) {
                wmma::fragment<wmma::matrix_b, 16, 16, 16, __nv_bfloat16, wmma::row_major> bh, bl;
                wmma::load_matrix_sync(bh, &cwh[wc * 32 + j * 16], QW_STR);
                wmma::load_matrix_sync(bl, &cwl[wc * 32 + j * 16], QW_STR);
                #pragma unroll
                for (int i = 0; i < 2; i++) {
                    wmma::mma_sync(acc[i][j], ah[i], bh, acc[i][j]);
                    wmma::mma_sync(acc[i][j], ah[i], bl, acc[i][j]);
                    wmma::mma_sync(acc[i][j], al[i], bh, acc[i][j]);
                }
            }
        }
        if (ks == 7) {
            if (mm == 0) {   // q: direct global store (bias already inside)
                #pragma unroll
                for (int i = 0; i < 2; i++)
                    #pragma unroll
                    for (int j = 0; j < 2; j++)
                        wmma::store_matrix_sync(
                            &g_q[(size_t)(row0 + wr * 32 + i * 16) * 128 + wc * 32 + j * 16],
                            acc[i][j], 128, wmma::mem_row_major);
            } else {
                #pragma unroll
                for (int i = 0; i < 2; i++)
                    #pragma unroll
                    for (int j = 0; j < 2; j++)
                        wmma::store_matrix_sync(
                            &outb[(wr * 32 + i * 16) * QO_STR + wc * 32 + j * 16],
                            acc[i][j], QO_STR, wmma::mem_row_major);
            }
        }
        __syncthreads();   // next-buffer stores + outb visible

        if (ks == 7 && mm > 0) {
            int b = ids_s[ep_r];
            if (b >= 0) {
                unsigned* p = ((mm == 1) ? g_kkey : g_vkey) + (size_t)b * 128;
                #pragma unroll 8
                for (int c = 0; c < 32; c++) {
                    int cc = ep_c0 + c;
                    atomicMax(&p[cc], fenc(outb[ep_r * QO_STR + cc]));
                }
            }
        }
    }

    // x_sum + counts (xs never overwritten)
    {
        int b = ids_s[ep_r];
        if (b >= 0) {
            float* dst = &g_xsum[(size_t)b * 128];
            #pragma unroll 8
            for (int c = 0; c < 32; c++) {
                int cc = ep_c0 + c;
                float v = __bfloat162float(xs_hi[ep_r * QX_STR + cc])
                        + __bfloat162float(xs_lo[ep_r * QX_STR + cc]);
                atomicAdd(&dst[cc], v);
            }
            if ((tid & 3) == 0) atomicAdd(&g_counts[b], 1.0f);
        }
    }
}

// ---------------- phase 2: centroid finalize + per-bucket Wvc GEMM ----------
__global__ void __launch_bounds__(256)
k_cent(const float* __restrict__ Wk,  const float* __restrict__ bk,
       const float* __restrict__ Wv,  const float* __restrict__ bv,
       const float* __restrict__ Wvc, const float* __restrict__ bvc) {
    __shared__ float vt[2][256];
    int tid = threadIdx.x;
    int bl = tid >> 7, c = tid & 127;
    int b = blockIdx.x * 2 + bl;

    float cnt = g_counts[b];
    float inv = 1.0f / fmaxf(cnt, 1.0f);
    const float* xs = &g_xsum[(size_t)b * 128];
    float ak = 0.0f, av = 0.0f;
    #pragma unroll 4
    for (int k = 0; k < 128; k++) {
        float xv = xs[k];
        ak = fmaf(xv, __ldg(&Wk[k * 128 + c]), ak);
        av = fmaf(xv, __ldg(&Wv[k * 128 + c]), av);
    }
    float kmean = (ak + cnt * __ldg(&bk[c])) * inv;
    float vmean = (av + cnt * __ldg(&bv[c])) * inv;
    bool ne = cnt > 0.0f;
    float kmax = ne ? fdec(g_kkey[(size_t)b * 128 + c]) : 0.0f;
    float vmax = ne ? fdec(g_vkey[(size_t)b * 128 + c]) : 0.0f;

    g_kc[(size_t)b * 256 + c]       = kmean;
    g_kc[(size_t)b * 256 + 128 + c] = kmax;
    vt[bl][c]       = vmean;
    vt[bl][128 + c] = vmax;
    __syncthreads();

    float a = 0.0f;
    #pragma unroll 4
    for (int k = 0; k < 256; k++)
        a = fmaf(vt[bl][k], __ldg(&Wvc[k * 128 + c]), a);
    g_vcomb[(size_t)b * 128 + c] = a + __ldg(&bvc[c]);
}

// ---------------- phase 3: wmma fused chain (32x32 warp tiles) --------------
#define I_STR 264
#define H_STR 136
#define FO_STR 132
#define W_STR 136
#define RGN 34816
#define SM_FUSED_BYTES (3 * RGN + 2 * 16 * W_STR * 2)   // 113152

__global__ void __launch_bounds__(256, 2)
k_fused(const void* __restrict__ ids, float* __restrict__ out, int n) {
    extern __shared__ unsigned char smraw[];
    __nv_bfloat16* ih  = (__nv_bfloat16*)(smraw);            // 64*264
    __nv_bfloat16* il  = (__nv_bfloat16*)(smraw + RGN);      // 64*264
    __nv_bfloat16* h1h = (__nv_bfloat16*)(smraw + 2 * RGN);  // 64*136
    __nv_bfloat16* h1l = h1h + 64 * H_STR;
    float*        outb = (float*)(smraw);                    // reuse RA
    __nv_bfloat16* tbh = (__nv_bfloat16*)(smraw + RGN);      // reuse RB
    __nv_bfloat16* tbl = tbh + 64 * H_STR;
    __nv_bfloat16* wsh = (__nv_bfloat16*)(smraw + 3 * RGN);  // 16*136
    __nv_bfloat16* wsl = wsh + 16 * W_STR;
    __shared__ int ids_s[64];

    const bool is64 = (g_or == 0u);
    const int tid = threadIdx.x;
    const int wid = tid >> 5;
    const int row0 = blockIdx.x * 64;
    const float scale = 0.17677669529663687f;   // (128/4)^-0.5
    const int wr = wid >> 2;            // 0..1 : rows wr*32
    const int wc = wid & 3;             // 0..3 : cols wc*32
    const int ep_r = tid >> 2;
    const int ep_c0 = (tid & 3) * 32;
    const int prow = tid >> 4;
    const int pcol = tid & 15;
    const bool full = (row0 + 64 <= n);

    if (tid < 64) {
        int r = row0 + tid;
        ids_s[tid] = (r < n) ? get_id(ids, r, is64) : -1;
    }
    __syncthreads();

    // prefetch GEMM1 chunk 0 (overlaps stage-a)
    uint4 ph = ((const uint4*)g_wg1h)[prow * 16 + pcol];
    uint4 pl = ((const uint4*)g_wg1l)[prow * 16 + pcol];

    // stage a: inter = [q,q]*kctx*scale -> bf16 hi/lo  (q already has bias)
    for (int t = tid; t < 64 * 64; t += 256) {
        int r = t >> 6, c4 = t & 63;
        int b = ids_s[r];
        float4 iv = make_float4(0.f, 0.f, 0.f, 0.f);
        if (b >= 0) {
            float4 qv = ((const float4*)g_q)[(size_t)(row0 + r) * 32 + (c4 & 31)];
            float4 kc = ((const float4*)g_kc)[(size_t)b * 64 + c4];
            iv.x = qv.x * kc.x * scale; iv.y = qv.y * kc.y * scale;
            iv.z = qv.z * kc.z * scale; iv.w = qv.w * kc.w * scale;
        }
        float vv[4] = {iv.x, iv.y, iv.z, iv.w};
        #pragma unroll
        for (int j = 0; j < 4; j++) {
            __nv_bfloat16 h, l;
            bfsplit(vv[j], h, l);
            ih[r * I_STR + c4 * 4 + j] = h;
            il[r * I_STR + c4 * 4 + j] = l;
        }
    }
    __syncthreads();
    *(uint4*)&wsh[prow * W_STR + pcol * 8] = ph;
    *(uint4*)&wsl[prow * W_STR + pcol * 8] = pl;
    __syncthreads();

    wmma::fragment<wmma::accumulator, 16, 16, 16, float> acc[2][2];

    // ---- GEMM1: h1 = relu(inter @ Wg1 + bg1), K=256, 16 chunks ----
    #pragma unroll
    for (int i = 0; i < 2; i++)
        #pragma unroll
        for (int j = 0; j < 2; j++)
            wmma::load_matrix_sync(acc[i][j], &g_btile[3][wc * 32 + j * 16], 128, wmma::mem_row_major);
    for (int t = 0; t < 16; t++) {
        int k0 = t * 16;
        if (t + 1 < 16) {
            ph = ((const uint4*)g_wg1h)[((t + 1) * 16 + prow) * 16 + pcol];
            pl = ((const uint4*)g_wg1l)[((t + 1) * 16 + prow) * 16 + pcol];
        }
        wmma::fragment<wmma::matrix_a, 16, 16, 16, __nv_bfloat16, wmma::row_major> ah[2], al[2];
        #pragma unroll
        for (int i = 0; i < 2; i++) {
            wmma::load_matrix_sync(ah[i], &ih[(wr * 32 + i * 16) * I_STR + k0], I_STR);
            wmma::load_matrix_sync(al[i], &il[(wr * 32 + i * 16) * I_STR + k0], I_STR);
        }
        #pragma unroll
        for (int j = 0; j < 2; j++) {
            wmma::fragment<wmma::matrix_b, 16, 16, 16, __nv_bfloat16, wmma::row_major> bh, bl;
            wmma::load_matrix_sync(bh, &wsh[wc * 32 + j * 16], W_STR);
            wmma::load_matrix_sync(bl, &wsl[wc * 32 + j * 16], W_STR);
            #pragma unroll
            for (int i = 0; i < 2; i++) {
                wmma::mma_sync(acc[i][j], ah[i], bh, acc[i][j]);
                wmma::mma_sync(acc[i][j], ah[i], bl, acc[i][j]);
                wmma::mma_sync(acc[i][j], al[i], bh, acc[i][j]);
            }
        }
        __syncthreads();
        if (t + 1 < 16) {
            *(uint4*)&wsh[prow * W_STR + pcol * 8] = ph;
            *(uint4*)&wsl[prow * W_STR + pcol * 8] = pl;
        }
        __syncthreads();
    }
    #pragma unroll
    for (int i = 0; i < 2; i++)
        #pragma unroll
        for (int j = 0; j < 2; j++)
            wmma::store_matrix_sync(&outb[(wr * 32 + i * 16) * FO_STR + wc * 32 + j * 16],
                                    acc[i][j], FO_STR, wmma::mem_row_major);
    __syncthreads();
    #pragma unroll 8
    for (int c = 0; c < 32; c++) {
        int cc = ep_c0 + c;
        float v = fmaxf(outb[ep_r * FO_STR + cc], 0.0f);   // bias already inside
        __nv_bfloat16 h, l;
        bfsplit(v, h, l);
        h1h[ep_r * H_STR + cc] = h;
        h1l[ep_r * H_STR + cc] = l;
    }

    // ---- GEMM2: gate = sigmoid(h1 @ Wg2 + bg2); tbuf = gate * vcomb ----
    ph = ((const uint4*)g_wg2h)[prow * 16 + pcol];
    pl = ((const uint4*)g_wg2l)[prow * 16 + pcol];
    __syncthreads();   // h1 writes + prior wbuf reads done
    *(uint4*)&wsh[prow * W_STR + pcol * 8] = ph;
    *(uint4*)&wsl[prow * W_STR + pcol * 8] = pl;
    __syncthreads();
    #pragma unroll
    for (int i = 0; i < 2; i++)
        #pragma unroll
        for (int j = 0; j < 2; j++)
            wmma::load_matrix_sync(acc[i][j], &g_btile[4][wc * 32 + j * 16], 128, wmma::mem_row_major);
    for (int t = 0; t < 8; t++) {
        int k0 = t * 16;
        if (t + 1 < 8) {
            ph = ((const uint4*)g_wg2h)[((t + 1) * 16 + prow) * 16 + pcol];
            pl = ((const uint4*)g_wg2l)[((t + 1) * 16 + prow) * 16 + pcol];
        }
        wmma::fragment<wmma::matrix_a, 16, 16, 16, __nv_bfloat16, wmma::row_major> ah[2], al[2];
        #pragma unroll
        for (int i = 0; i < 2; i++) {
            wmma::load_matrix_sync(ah[i], &h1h[(wr * 32 + i * 16) * H_STR + k0], H_STR);
            wmma::load_matrix_sync(al[i], &h1l[(wr * 32 + i * 16) * H_STR + k0], H_STR);
        }
        #pragma unroll
        for (int j = 0; j < 2; j++) {
            wmma::fragment<wmma::matrix_b, 16, 16, 16, __nv_bfloat16, wmma::row_major> bh, bl;
            wmma::load_matrix_sync(bh, &wsh[wc * 32 + j * 16], W_STR);
            wmma::load_matrix_sync(bl, &wsl[wc * 32 + j * 16], W_STR);
            #pragma unroll
            for (int i = 0; i < 2; i++) {
                wmma::mma_sync(acc[i][j], ah[i], bh, acc[i][j]);
                wmma::mma_sync(acc[i][j], ah[i], bl, acc[i][j]);
                wmma::mma_sync(acc[i][j], al[i], bh, acc[i][j]);
            }
        }
        __syncthreads();
        if (t + 1 < 8) {
            *(uint4*)&wsh[prow * W_STR + pcol * 8] = ph;
            *(uint4*)&wsl[prow * W_STR + pcol * 8] = pl;
        }
        __syncthreads();
    }
    #pragma unroll
    for (int i = 0; i < 2; i++)
        #pragma unroll
        for (int j = 0; j < 2; j++)
            wmma::store_matrix_sync(&outb[(wr * 32 + i * 16) * FO_STR + wc * 32 + j * 16],
                                    acc[i][j], FO_STR, wmma::mem_row_major);
    __syncthreads();
    {
        int b = ids_s[ep_r];
        #pragma unroll 8
        for (int c = 0; c < 32; c++) {
            int cc = ep_c0 + c;
            float gate = 1.0f / (1.0f + __expf(-outb[ep_r * FO_STR + cc]));  // bias inside
            float vc = (b >= 0) ? g_vcomb[(size_t)b * 128 + cc] : 0.0f;
            __nv_bfloat16 h, l;
            bfsplit(gate * vc, h, l);
            tbh[ep_r * H_STR + cc] = h;
            tbl[ep_r * H_STR + cc] = l;
        }
    }

    // ---- GEMM3: out = tbuf @ Wp + bp ----
    ph = ((const uint4*)g_wph)[prow * 16 + pcol];
    pl = ((const uint4*)g_wpl)[prow * 16 + pcol];
    __syncthreads();   // tbuf writes + prior wbuf reads done
    *(uint4*)&wsh[prow * W_STR + pcol * 8] = ph;
    *(uint4*)&wsl[prow * W_STR + pcol * 8] = pl;
    __syncthreads();
    #pragma unroll
    for (int i = 0; i < 2; i++)
        #pragma unroll
        for (int j = 0; j < 2; j++)
            wmma::load_matrix_sync(acc[i][j], &g_btile[5][wc * 32 + j * 16], 128, wmma::mem_row_major);
    for (int t = 0; t < 8; t++) {
        int k0 = t * 16;
        if (t + 1 < 8) {
            ph = ((const uint4*)g_wph)[((t + 1) * 16 + prow) * 16 + pcol];
            pl = ((const uint4*)g_wpl)[((t + 1) * 16 + prow) * 16 + pcol];
        }
        wmma::fragment<wmma::matrix_a, 16, 16, 16, __nv_bfloat16, wmma::row_major> ah[2], al[2];
        #pragma unroll
        for (int i = 0; i < 2; i++) {
            wmma::load_matrix_sync(ah[i], &tbh[(wr * 32 + i * 16) * H_STR + k0], H_STR);
            wmma::load_matrix_sync(al[i], &tbl[(wr * 32 + i * 16) * H_STR + k0], H_STR);
        }
        #pragma unroll
        for (int j = 0; j < 2; j++) {
            wmma::fragment<wmma::matrix_b, 16, 16, 16, __nv_bfloat16, wmma::row_major> bh, bl;
            wmma::load_matrix_sync(bh, &wsh[wc * 32 + j * 16], W_STR);
            wmma::load_matrix_sync(bl, &wsl[wc * 32 + j * 16], W_STR);
            #pragma unroll
            for (int i = 0; i < 2; i++) {
                wmma::mma_sync(acc[i][j], ah[i], bh, acc[i][j]);
                wmma::mma_sync(acc[i][j], ah[i], bl, acc[i][j]);
                wmma::mma_sync(acc[i][j], al[i], bh, acc[i][j]);
            }
        }
        __syncthreads();
        if (t + 1 < 8) {
            *(uint4*)&wsh[prow * W_STR + pcol * 8] = ph;
            *(uint4*)&wsl[prow * W_STR + pcol * 8] = pl;
        }
        __syncthreads();
    }
    if (full) {
        // direct global store (bias already inside accumulators)
        #pragma unroll
        for (int i = 0; i < 2; i++)
            #pragma unroll
            for (int j = 0; j < 2; j++)
                wmma::store_matrix_sync(
                    &out[(size_t)(row0 + wr * 32 + i * 16) * 128 + wc * 32 + j * 16],
                    acc[i][j], 128, wmma::mem_row_major);
    } else {
        #pragma unroll
        for (int i = 0; i < 2; i++)
            #pragma unroll
            for (int j = 0; j < 2; j++)
                wmma::store_matrix_sync(&outb[(wr * 32 + i * 16) * FO_STR + wc * 32 + j * 16],
                                        acc[i][j], FO_STR, wmma::mem_row_major);
        __syncthreads();
        int grow = row0 + ep_r;
        if (grow < n) {
            float* op = &out[(size_t)grow * 128];
            #pragma unroll
            for (int c = 0; c < 32; c += 4) {
                int cc = ep_c0 + c;
                float4 o = *(const float4*)&outb[ep_r * FO_STR + cc];
                *(float4*)&op[cc] = o;
            }
        }
    }
}

// ---------------- launch ----------------------------------------------------
extern "C" void kernel_launch(void* const* d_in, const int* in_sizes, int n_in,
                              void* d_out, int out_size) {
    const float* x   = (const float*)d_in[0];
    const void*  ids = d_in[1];
    // d_in[2] = total_buckets (constant 8192, unused)
    const float *Wq = (const float*)d_in[3],  *bq = (const float*)d_in[4];
    const float *Wk = (const float*)d_in[5],  *bk = (const float*)d_in[6];
    const float *Wv = (const float*)d_in[7],  *bv = (const float*)d_in[8];
    const float *Wg1 = (const float*)d_in[9], *bg1 = (const float*)d_in[10];
    const float *Wg2 = (const float*)d_in[11], *bg2 = (const float*)d_in[12];
    const float *Wvc = (const float*)d_in[13], *bvc = (const float*)d_in[14];
    const float *Wp  = (const float*)d_in[15], *bp  = (const float*)d_in[16];
    float* out = (float*)d_out;

    const int n = in_sizes[0] / CC;

    static int smem_set = 0;
    if (!smem_set) {
        cudaFuncSetAttribute(k_qkv,   cudaFuncAttributeMaxDynamicSharedMemorySize, SM_QKV_BYTES);
        cudaFuncSetAttribute(k_fused, cudaFuncAttributeMaxDynamicSharedMemorySize, SM_FUSED_BYTES);
        smem_set = 1;
    }

    k_init<<<512, 256>>>();
    k_detect<<<256, 256>>>((const unsigned*)ids, in_sizes[1]);
    k_prep<<<496, 256>>>(Wq, Wk, Wv, Wg1, Wg2, Wp, bq, bk, bv, bg1, bg2, bp);

    int g1 = (n + 63) / 64;
    k_qkv<<<g1, 256, SM_QKV_BYTES>>>(x, ids, n);

    k_cent<<<BKT / 2, 256>>>(Wk, bk, Wv, bv, Wvc, bvc);

    k_fused<<<g1, 256, SM_FUSED_BYTES>>>(ids, out, n);
}

// round 17
// speedup vs baseline: 1.3562x; 1.0318x over previous
#include <cuda_runtime.h>
#include <cuda_bf16.h>
#include <mma.h>
#include <cstdint>

using namespace nvcuda;

#define CC   128
#define BKT  8192
#define NMAX 500000

// ---------------- scratch (__device__ globals; no allocs allowed) ----------
__device__ float    g_q[(size_t)(NMAX + 128) * CC];  // padded for edge-tile store
__device__ float    g_xsum[BKT * CC];
__device__ unsigned g_kkey[BKT * CC];
__device__ unsigned g_vkey[BKT * CC];
__device__ float    g_counts[BKT];
__device__ float    g_kc[BKT * 2 * CC];          // [k_mean | k_max] per bucket
__device__ float    g_vcomb[BKT * CC];           // [v_mean|v_max] @ Wvc + bvc
__device__ unsigned g_or;                        // 0 => ids are int64
// pre-split weights (bf16 hi/lo, row-major ldm=128)
__device__ __align__(256) __nv_bfloat16 g_wqh[128 * 128], g_wql[128 * 128];
__device__ __align__(256) __nv_bfloat16 g_wkh[128 * 128], g_wkl[128 * 128];
__device__ __align__(256) __nv_bfloat16 g_wvh[128 * 128], g_wvl[128 * 128];
__device__ __align__(256) __nv_bfloat16 g_wg1h[256 * 128], g_wg1l[256 * 128];
__device__ __align__(256) __nv_bfloat16 g_wg2h[128 * 128], g_wg2l[128 * 128];
__device__ __align__(256) __nv_bfloat16 g_wph[128 * 128],  g_wpl[128 * 128];
// bias tiles: 16 identical rows of each bias (bq,bk,bv,bg1,bg2,bp)
__device__ __align__(256) float g_btile[6][16 * 128];

// monotonic float<->uint mapping for atomicMax on floats
__device__ __forceinline__ unsigned fenc(float f) {
    unsigned u = __float_as_uint(f);
    return (u & 0x80000000u) ? ~u : (u | 0x80000000u);
}
__device__ __forceinline__ float fdec(unsigned e) {
    return (e & 0x80000000u) ? __uint_as_float(e ^ 0x80000000u)
                             : __uint_as_float(~e);
}
__device__ __forceinline__ int get_id(const void* ids, int i, bool is64) {
    return is64 ? (int)((const long long*)ids)[i] : ((const int*)ids)[i];
}
__device__ __forceinline__ void bfsplit(float v, __nv_bfloat16& h, __nv_bfloat16& l) {
    h = __float2bfloat16(v);
    l = __float2bfloat16(v - __bfloat162float(h));
}

// ---------------- init ------------------------------------------------------
__global__ void k_init() {
    size_t i = (size_t)blockIdx.x * blockDim.x + threadIdx.x;
    size_t stride = (size_t)gridDim.x * blockDim.x;
    for (size_t t = i; t < (size_t)BKT * CC; t += stride) {
        g_xsum[t] = 0.0f; g_kkey[t] = 0u; g_vkey[t] = 0u;
    }
    for (size_t t = i; t < BKT; t += stride) g_counts[t] = 0.0f;
    if (i == 0) g_or = 0u;
}

// ---------------- id dtype detection ---------------------------------------
__global__ void k_detect(const unsigned* __restrict__ w, int nwords) {
    unsigned acc = 0;
    int gid = blockIdx.x * blockDim.x + threadIdx.x;
    int stride = gridDim.x * blockDim.x;
    for (int t = 1 + 2 * gid; t < nwords; t += 2 * stride) acc |= w[t];
    for (int o = 16; o; o >>= 1) acc |= __shfl_xor_sync(0xFFFFFFFFu, acc, o);
    if ((threadIdx.x & 31) == 0 && acc) atomicOr(&g_or, acc);
}

// ---------------- weight prep: splits + bias tiles --------------------------
__global__ void k_prep(const float* __restrict__ Wq, const float* __restrict__ Wk,
                       const float* __restrict__ Wv, const float* __restrict__ Wg1,
                       const float* __restrict__ Wg2, const float* __restrict__ Wp,
                       const float* __restrict__ bq, const float* __restrict__ bk,
                       const float* __restrict__ bv, const float* __restrict__ bg1,
                       const float* __restrict__ bg2, const float* __restrict__ bp) {
    int t = blockIdx.x * 256 + threadIdx.x;     // 114688 weights + 12288 bias
    if (t >= 114688 + 12288) return;
    if (t >= 114688) {
        int t2 = t - 114688;
        int which = t2 >> 11, idx = t2 & 2047, c = idx & 127;
        const float* Bs[6] = {bq, bk, bv, bg1, bg2, bp};
        g_btile[which][idx] = Bs[which][c];
        return;
    }
    __nv_bfloat16 h, l;
    if (t < 16384) {
        bfsplit(Wq[t], h, l); g_wqh[t] = h; g_wql[t] = l;
    } else if (t < 32768) {
        int i = t - 16384;
        bfsplit(Wk[i], h, l); g_wkh[i] = h; g_wkl[i] = l;
    } else if (t < 49152) {
        int i = t - 32768;
        bfsplit(Wv[i], h, l); g_wvh[i] = h; g_wvl[i] = l;
    } else if (t < 81920) {
        int i = t - 49152;
        bfsplit(Wg1[i], h, l); g_wg1h[i] = h; g_wg1l[i] = l;
    } else if (t < 98304) {
        int i = t - 81920;
        bfsplit(Wg2[i], h, l); g_wg2h[i] = h; g_wg2l[i] = l;
    } else {
        int i = t - 98304;
        bfsplit(Wp[i], h, l);  g_wph[i] = h;  g_wpl[i] = l;
    }
}

// ---------------- phase 1: wmma qkv, 128x128 CTA tile, 32x64 warp tiles -----
#define QX_STR 136
#define QW_STR 136
#define QO_STR 132
#define SM_QKV_BYTES (2 * 128 * QX_STR * 2 + 2 * 16 * QW_STR * 2 + 64 * QO_STR * 4) // 112128

__global__ void __launch_bounds__(256, 2)
k_qkv(const float* __restrict__ x, const void* __restrict__ ids, int n) {
    extern __shared__ unsigned char smraw[];
    __nv_bfloat16* xs_hi = (__nv_bfloat16*)smraw;                  // 128*136
    __nv_bfloat16* xs_lo = xs_hi + 128 * QX_STR;
    __nv_bfloat16* wsh   = xs_lo + 128 * QX_STR;                   // 16*136
    __nv_bfloat16* wsl   = wsh + 16 * QW_STR;
    float*         outb  = (float*)(wsl + 16 * QW_STR);            // 64*132
    __shared__ int ids_s[128];

    const bool is64 = (g_or == 0u);
    const int tid = threadIdx.x;
    const int wid = tid >> 5;
    const int row0 = blockIdx.x * 128;
    const int wr = wid >> 1;            // 0..3 : rows wr*32
    const int wc = wid & 1;             // 0..1 : cols wc*64
    const int ep_r = tid >> 2;          // 0..63 (within half)
    const int ep_c0 = (tid & 3) * 32;   // 32 cols
    const int prow = tid >> 4;          // staging row 0..15
    const int pcol = tid & 15;          // staging uint4 col

    const __nv_bfloat16* WHs[3] = {g_wqh, g_wkh, g_wvh};
    const __nv_bfloat16* WLs[3] = {g_wql, g_wkl, g_wvl};

    if (tid < 128) {
        int r = row0 + tid;
        ids_s[tid] = (r < n) ? get_id(ids, r, is64) : -1;
    }

    // prefetch chunk 0 (overlaps x conversion)
    uint4 ph = ((const uint4*)WHs[0])[prow * 16 + pcol];
    uint4 pl = ((const uint4*)WLs[0])[prow * 16 + pcol];

    // x tile (128 rows) -> bf16 hi/lo
    for (int t = tid; t < 128 * 32; t += 256) {
        int r = t >> 5, c4 = t & 31;
        float4 v = make_float4(0.f, 0.f, 0.f, 0.f);
        if (row0 + r < n) v = ((const float4*)x)[(size_t)(row0 + r) * 32 + c4];
        float vv[4] = {v.x, v.y, v.z, v.w};
        #pragma unroll
        for (int j = 0; j < 4; j++) {
            __nv_bfloat16 h, l;
            bfsplit(vv[j], h, l);
            xs_hi[r * QX_STR + c4 * 4 + j] = h;
            xs_lo[r * QX_STR + c4 * 4 + j] = l;
        }
    }
    *(uint4*)&wsh[prow * QW_STR + pcol * 8] = ph;
    *(uint4*)&wsl[prow * QW_STR + pcol * 8] = pl;
    __syncthreads();

    wmma::fragment<wmma::accumulator, 16, 16, 16, float> acc[2][4];

    for (int t = 0; t < 24; t++) {
        const int mm = t >> 3, ks = t & 7, k0 = ks * 16;

        if (ks == 0) {   // bias-initialized accumulators
            #pragma unroll
            for (int i = 0; i < 2; i++)
                #pragma unroll
                for (int j = 0; j < 4; j++)
                    wmma::load_matrix_sync(acc[i][j], &g_btile[mm][wc * 64 + j * 16],
                                           128, wmma::mem_row_major);
        }
        if (t + 1 < 24) {   // prefetch next chunk into registers (overlaps MMA)
            int m2 = (t + 1) >> 3, k2 = ((t + 1) & 7) * 16;
            ph = ((const uint4*)WHs[m2])[(k2 + prow) * 16 + pcol];
            pl = ((const uint4*)WLs[m2])[(k2 + prow) * 16 + pcol];
        }
        {
            wmma::fragment<wmma::matrix_a, 16, 16, 16, __nv_bfloat16, wmma::row_major> ah[2], al[2];
            #pragma unroll
            for (int i = 0; i < 2; i++) {
                wmma::load_matrix_sync(ah[i], &xs_hi[(wr * 32 + i * 16) * QX_STR + k0], QX_STR);
                wmma::load_matrix_sync(al[i], &xs_lo[(wr * 32 + i * 16) * QX_STR + k0], QX_STR);
            }
            #pragma unroll
            for (int j = 0; j < 4; j++) {
                wmma::fragment<wmma::matrix_b, 16, 16, 16, __nv_bfloat16, wmma::row_major> bh, bl;
                wmma::load_matrix_sync(bh, &wsh[wc * 64 + j * 16], QW_STR);
                wmma::load_matrix_sync(bl, &wsl[wc * 64 + j * 16], QW_STR);
                #pragma unroll
                for (int i = 0; i < 2; i++) {
                    wmma::mma_sync(acc[i][j], ah[i], bh, acc[i][j]);
                    wmma::mma_sync(acc[i][j], ah[i], bl, acc[i][j]);
                    wmma::mma_sync(acc[i][j], al[i], bh, acc[i][j]);
                }
            }
        }
        __syncthreads();   // wbuf reads of chunk t done
        if (t + 1 < 24) {
            *(uint4*)&wsh[prow * QW_STR + pcol * 8] = ph;
            *(uint4*)&wsl[prow * QW_STR + pcol * 8] = pl;
        }

        if (ks == 7) {
            if (mm == 0) {   // q: direct global store (bias inside; rows padded)
                #pragma unroll
                for (int i = 0; i < 2; i++)
                    #pragma unroll
                    for (int j = 0; j < 4; j++)
                        wmma::store_matrix_sync(
                            &g_q[(size_t)(row0 + wr * 32 + i * 16) * 128 + wc * 64 + j * 16],
                            acc[i][j], 128, wmma::mem_row_major);
                __syncthreads();   // wbuf stores visible
            } else {
                // half 0: rows 0..63 (warps wr 0..1)
                if (wr < 2) {
                    #pragma unroll
                    for (int i = 0; i < 2; i++)
                        #pragma unroll
                        for (int j = 0; j < 4; j++)
                            wmma::store_matrix_sync(
                                &outb[(wr * 32 + i * 16) * QO_STR + wc * 64 + j * 16],
                                acc[i][j], QO_STR, wmma::mem_row_major);
                }
                __syncthreads();
                {
                    int b = ids_s[ep_r];
                    if (b >= 0) {
                        unsigned* p = ((mm == 1) ? g_kkey : g_vkey) + (size_t)b * 128;
                        #pragma unroll 8
                        for (int c = 0; c < 32; c++) {
                            int cc = ep_c0 + c;
                            atomicMax(&p[cc], fenc(outb[ep_r * QO_STR + cc]));
                        }
                    }
                }
                __syncthreads();
                // half 1: rows 64..127 (warps wr 2..3)
                if (wr >= 2) {
                    #pragma unroll
                    for (int i = 0; i < 2; i++)
                        #pragma unroll
                        for (int j = 0; j < 4; j++)
                            wmma::store_matrix_sync(
                                &outb[((wr - 2) * 32 + i * 16) * QO_STR + wc * 64 + j * 16],
                                acc[i][j], QO_STR, wmma::mem_row_major);
                }
                __syncthreads();
                {
                    int b = ids_s[64 + ep_r];
                    if (b >= 0) {
                        unsigned* p = ((mm == 1) ? g_kkey : g_vkey) + (size_t)b * 128;
                        #pragma unroll 8
                        for (int c = 0; c < 32; c++) {
                            int cc = ep_c0 + c;
                            atomicMax(&p[cc], fenc(outb[ep_r * QO_STR + cc]));
                        }
                    }
                }
                __syncthreads();
            }
        } else {
            __syncthreads();   // wbuf stores visible before next chunk MMA
        }
    }

    // x_sum + counts (xs never overwritten), both halves
    #pragma unroll
    for (int h = 0; h < 2; h++) {
        int r = h * 64 + ep_r;
        int b = ids_s[r];
        if (b >= 0) {
            float* dst = &g_xsum[(size_t)b * 128];
            #pragma unroll 8
            for (int c = 0; c < 32; c++) {
                int cc = ep_c0 + c;
                float v = __bfloat162float(xs_hi[r * QX_STR + cc])
                        + __bfloat162float(xs_lo[r * QX_STR + cc]);
                atomicAdd(&dst[cc], v);
            }
            if ((tid & 3) == 0) atomicAdd(&g_counts[b], 1.0f);
        }
    }
}

// ---------------- phase 2: centroid finalize + per-bucket Wvc GEMM ----------
__global__ void __launch_bounds__(256)
k_cent(const float* __restrict__ Wk,  const float* __restrict__ bk,
       const float* __restrict__ Wv,  const float* __restrict__ bv,
       const float* __restrict__ Wvc, const float* __restrict__ bvc) {
    __shared__ float vt[2][256];
    int tid = threadIdx.x;
    int bl = tid >> 7, c = tid & 127;
    int b = blockIdx.x * 2 + bl;

    float cnt = g_counts[b];
    float inv = 1.0f / fmaxf(cnt, 1.0f);
    const float* xs = &g_xsum[(size_t)b * 128];
    float ak = 0.0f, av = 0.0f;
    #pragma unroll 4
    for (int k = 0; k < 128; k++) {
        float xv = xs[k];
        ak = fmaf(xv, __ldg(&Wk[k * 128 + c]), ak);
        av = fmaf(xv, __ldg(&Wv[k * 128 + c]), av);
    }
    float kmean = (ak + cnt * __ldg(&bk[c])) * inv;
    float vmean = (av + cnt * __ldg(&bv[c])) * inv;
    bool ne = cnt > 0.0f;
    float kmax = ne ? fdec(g_kkey[(size_t)b * 128 + c]) : 0.0f;
    float vmax = ne ? fdec(g_vkey[(size_t)b * 128 + c]) : 0.0f;

    g_kc[(size_t)b * 256 + c]       = kmean;
    g_kc[(size_t)b * 256 + 128 + c] = kmax;
    vt[bl][c]       = vmean;
    vt[bl][128 + c] = vmax;
    __syncthreads();

    float a = 0.0f;
    #pragma unroll 4
    for (int k = 0; k < 256; k++)
        a = fmaf(vt[bl][k], __ldg(&Wvc[k * 128 + c]), a);
    g_vcomb[(size_t)b * 128 + c] = a + __ldg(&bvc[c]);
}

// ---------------- phase 3: wmma fused chain (R15 winner, unchanged) ---------
#define I_STR 264
#define H_STR 136
#define FO_STR 132
#define W_STR 136
#define RGN 34816
#define SM_FUSED_BYTES (3 * RGN + 2 * 16 * W_STR * 2)   // 113152

__global__ void __launch_bounds__(256, 2)
k_fused(const void* __restrict__ ids, float* __restrict__ out, int n) {
    extern __shared__ unsigned char smraw[];
    __nv_bfloat16* ih  = (__nv_bfloat16*)(smraw);            // 64*264
    __nv_bfloat16* il  = (__nv_bfloat16*)(smraw + RGN);      // 64*264
    __nv_bfloat16* h1h = (__nv_bfloat16*)(smraw + 2 * RGN);  // 64*136
    __nv_bfloat16* h1l = h1h + 64 * H_STR;
    float*        outb = (float*)(smraw);                    // reuse RA
    __nv_bfloat16* tbh = (__nv_bfloat16*)(smraw + RGN);      // reuse RB
    __nv_bfloat16* tbl = tbh + 64 * H_STR;
    __nv_bfloat16* wsh = (__nv_bfloat16*)(smraw + 3 * RGN);  // 16*136
    __nv_bfloat16* wsl = wsh + 16 * W_STR;
    __shared__ int ids_s[64];

    const bool is64 = (g_or == 0u);
    const int tid = threadIdx.x;
    const int wid = tid >> 5;
    const int row0 = blockIdx.x * 64;
    const float scale = 0.17677669529663687f;   // (128/4)^-0.5
    const int wr = wid >> 2;            // 0..1 : rows wr*32
    const int wc = wid & 3;             // 0..3 : cols wc*32
    const int ep_r = tid >> 2;
    const int ep_c0 = (tid & 3) * 32;
    const int prow = tid >> 4;
    const int pcol = tid & 15;
    const bool full = (row0 + 64 <= n);

    if (tid < 64) {
        int r = row0 + tid;
        ids_s[tid] = (r < n) ? get_id(ids, r, is64) : -1;
    }
    __syncthreads();

    // prefetch GEMM1 chunk 0 (overlaps stage-a)
    uint4 ph = ((const uint4*)g_wg1h)[prow * 16 + pcol];
    uint4 pl = ((const uint4*)g_wg1l)[prow * 16 + pcol];

    // stage a: inter = [q,q]*kctx*scale -> bf16 hi/lo  (q already has bias)
    for (int t = tid; t < 64 * 64; t += 256) {
        int r = t >> 6, c4 = t & 63;
        int b = ids_s[r];
        float4 iv = make_float4(0.f, 0.f, 0.f, 0.f);
        if (b >= 0) {
            float4 qv = ((const float4*)g_q)[(size_t)(row0 + r) * 32 + (c4 & 31)];
            float4 kc = ((const float4*)g_kc)[(size_t)b * 64 + c4];
            iv.x = qv.x * kc.x * scale; iv.y = qv.y * kc.y * scale;
            iv.z = qv.z * kc.z * scale; iv.w = qv.w * kc.w * scale;
        }
        float vv[4] = {iv.x, iv.y, iv.z, iv.w};
        #pragma unroll
        for (int j = 0; j < 4; j++) {
            __nv_bfloat16 h, l;
            bfsplit(vv[j], h, l);
            ih[r * I_STR + c4 * 4 + j] = h;
            il[r * I_STR + c4 * 4 + j] = l;
        }
    }
    __syncthreads();
    *(uint4*)&wsh[prow * W_STR + pcol * 8] = ph;
    *(uint4*)&wsl[prow * W_STR + pcol * 8] = pl;
    __syncthreads();

    wmma::fragment<wmma::accumulator, 16, 16, 16, float> acc[2][2];

    // ---- GEMM1: h1 = relu(inter @ Wg1 + bg1), K=256, 16 chunks ----
    #pragma unroll
    for (int i = 0; i < 2; i++)
        #pragma unroll
        for (int j = 0; j < 2; j++)
            wmma::load_matrix_sync(acc[i][j], &g_btile[3][wc * 32 + j * 16], 128, wmma::mem_row_major);
    for (int t = 0; t < 16; t++) {
        int k0 = t * 16;
        if (t + 1 < 16) {
            ph = ((const uint4*)g_wg1h)[((t + 1) * 16 + prow) * 16 + pcol];
            pl = ((const uint4*)g_wg1l)[((t + 1) * 16 + prow) * 16 + pcol];
        }
        wmma::fragment<wmma::matrix_a, 16, 16, 16, __nv_bfloat16, wmma::row_major> ah[2], al[2];
        #pragma unroll
        for (int i = 0; i < 2; i++) {
            wmma::load_matrix_sync(ah[i], &ih[(wr * 32 + i * 16) * I_STR + k0], I_STR);
            wmma::load_matrix_sync(al[i], &il[(wr * 32 + i * 16) * I_STR + k0], I_STR);
        }
        #pragma unroll
        for (int j = 0; j < 2; j++) {
            wmma::fragment<wmma::matrix_b, 16, 16, 16, __nv_bfloat16, wmma::row_major> bh, bl;
            wmma::load_matrix_sync(bh, &wsh[wc * 32 + j * 16], W_STR);
            wmma::load_matrix_sync(bl, &wsl[wc * 32 + j * 16], W_STR);
            #pragma unroll
            for (int i = 0; i < 2; i++) {
                wmma::mma_sync(acc[i][j], ah[i], bh, acc[i][j]);
                wmma::mma_sync(acc[i][j], ah[i], bl, acc[i][j]);
                wmma::mma_sync(acc[i][j], al[i], bh, acc[i][j]);
            }
        }
        __syncthreads();
        if (t + 1 < 16) {
            *(uint4*)&wsh[prow * W_STR + pcol * 8] = ph;
            *(uint4*)&wsl[prow * W_STR + pcol * 8] = pl;
        }
        __syncthreads();
    }
    #pragma unroll
    for (int i = 0; i < 2; i++)
        #pragma unroll
        for (int j = 0; j < 2; j++)
            wmma::store_matrix_sync(&outb[(wr * 32 + i * 16) * FO_STR + wc * 32 + j * 16],
                                    acc[i][j], FO_STR, wmma::mem_row_major);
    __syncthreads();
    #pragma unroll 8
    for (int c = 0; c < 32; c++) {
        int cc = ep_c0 + c;
        float v = fmaxf(outb[ep_r * FO_STR + cc], 0.0f);   // bias already inside
        __nv_bfloat16 h, l;
        bfsplit(v, h, l);
        h1h[ep_r * H_STR + cc] = h;
        h1l[ep_r * H_STR + cc] = l;
    }

    // ---- GEMM2: gate = sigmoid(h1 @ Wg2 + bg2); tbuf = gate * vcomb ----
    ph = ((const uint4*)g_wg2h)[prow * 16 + pcol];
    pl = ((const uint4*)g_wg2l)[prow * 16 + pcol];
    __syncthreads();   // h1 writes + prior wbuf reads done
    *(uint4*)&wsh[prow * W_STR + pcol * 8] = ph;
    *(uint4*)&wsl[prow * W_STR + pcol * 8] = pl;
    __syncthreads();
    #pragma unroll
    for (int i = 0; i < 2; i++)
        #pragma unroll
        for (int j = 0; j < 2; j++)
            wmma::load_matrix_sync(acc[i][j], &g_btile[4][wc * 32 + j * 16], 128, wmma::mem_row_major);
    for (int t = 0; t < 8; t++) {
        int k0 = t * 16;
        if (t + 1 < 8) {
            ph = ((const uint4*)g_wg2h)[((t + 1) * 16 + prow) * 16 + pcol];
            pl = ((const uint4*)g_wg2l)[((t + 1) * 16 + prow) * 16 + pcol];
        }
        wmma::fragment<wmma::matrix_a, 16, 16, 16, __nv_bfloat16, wmma::row_major> ah[2], al[2];
        #pragma unroll
        for (int i = 0; i < 2; i++) {
            wmma::load_matrix_sync(ah[i], &h1h[(wr * 32 + i * 16) * H_STR + k0], H_STR);
            wmma::load_matrix_sync(al[i], &h1l[(wr * 32 + i * 16) * H_STR + k0], H_STR);
        }
        #pragma unroll
        for (int j = 0; j < 2; j++) {
            wmma::fragment<wmma::matrix_b, 16, 16, 16, __nv_bfloat16, wmma::row_major> bh, bl;
            wmma::load_matrix_sync(bh, &wsh[wc * 32 + j * 16], W_STR);
            wmma::load_matrix_sync(bl, &wsl[wc * 32 + j * 16], W_STR);
            #pragma unroll
            for (int i = 0; i < 2; i++) {
                wmma::mma_sync(acc[i][j], ah[i], bh, acc[i][j]);
                wmma::mma_sync(acc[i][j], ah[i], bl, acc[i][j]);
                wmma::mma_sync(acc[i][j], al[i], bh, acc[i][j]);
            }
        }
        __syncthreads();
        if (t + 1 < 8) {
            *(uint4*)&wsh[prow * W_STR + pcol * 8] = ph;
            *(uint4*)&wsl[prow * W_STR + pcol * 8] = pl;
        }
        __syncthreads();
    }
    #pragma unroll
    for (int i = 0; i < 2; i++)
        #pragma unroll
        for (int j = 0; j < 2; j++)
            wmma::store_matrix_sync(&outb[(wr * 32 + i * 16) * FO_STR + wc * 32 + j * 16],
                                    acc[i][j], FO_STR, wmma::mem_row_major);
    __syncthreads();
    {
        int b = ids_s[ep_r];
        #pragma unroll 8
        for (int c = 0; c < 32; c++) {
            int cc = ep_c0 + c;
            float gate = 1.0f / (1.0f + __expf(-outb[ep_r * FO_STR + cc]));  // bias inside
            float vc = (b >= 0) ? g_vcomb[(size_t)b * 128 + cc] : 0.0f;
            __nv_bfloat16 h, l;
            bfsplit(gate * vc, h, l);
            tbh[ep_r * H_STR + cc] = h;
            tbl[ep_r * H_STR + cc] = l;
        }
    }

    // ---- GEMM3: out = tbuf @ Wp + bp ----
    ph = ((const uint4*)g_wph)[prow * 16 + pcol];
    pl = ((const uint4*)g_wpl)[prow * 16 + pcol];
    __syncthreads();   // tbuf writes + prior wbuf reads done
    *(uint4*)&wsh[prow * W_STR + pcol * 8] = ph;
    *(uint4*)&wsl[prow * W_STR + pcol * 8] = pl;
    __syncthreads();
    #pragma unroll
    for (int i = 0; i < 2; i++)
        #pragma unroll
        for (int j = 0; j < 2; j++)
            wmma::load_matrix_sync(acc[i][j], &g_btile[5][wc * 32 + j * 16], 128, wmma::mem_row_major);
    for (int t = 0; t < 8; t++) {
        int k0 = t * 16;
        if (t + 1 < 8) {
            ph = ((const uint4*)g_wph)[((t + 1) * 16 + prow) * 16 + pcol];
            pl = ((const uint4*)g_wpl)[((t + 1) * 16 + prow) * 16 + pcol];
        }
        wmma::fragment<wmma::matrix_a, 16, 16, 16, __nv_bfloat16, wmma::row_major> ah[2], al[2];
        #pragma unroll
        for (int i = 0; i < 2; i++) {
            wmma::load_matrix_sync(ah[i], &tbh[(wr * 32 + i * 16) * H_STR + k0], H_STR);
            wmma::load_matrix_sync(al[i], &tbl[(wr * 32 + i * 16) * H_STR + k0], H_STR);
        }
        #pragma unroll
        for (int j = 0; j < 2; j++) {
            wmma::fragment<wmma::matrix_b, 16, 16, 16, __nv_bfloat16, wmma::row_major> bh, bl;
            wmma::load_matrix_sync(bh, &wsh[wc * 32 + j * 16], W_STR);
            wmma::load_matrix_sync(bl, &wsl[wc * 32 + j * 16], W_STR);
            #pragma unroll
            for (int i = 0; i < 2; i++) {
                wmma::mma_sync(acc[i][j], ah[i], bh, acc[i][j]);
                wmma::mma_sync(acc[i][j], ah[i], bl, acc[i][j]);
                wmma::mma_sync(acc[i][j], al[i], bh, acc[i][j]);
            }
        }
        __syncthreads();
        if (t + 1 < 8) {
            *(uint4*)&wsh[prow * W_STR + pcol * 8] = ph;
            *(uint4*)&wsl[prow * W_STR + pcol * 8] = pl;
        }
        __syncthreads();
    }
    if (full) {
        // direct global store (bias already inside accumulators)
        #pragma unroll
        for (int i = 0; i < 2; i++)
            #pragma unroll
            for (int j = 0; j < 2; j++)
                wmma::store_matrix_sync(
                    &out[(size_t)(row0 + wr * 32 + i * 16) * 128 + wc * 32 + j * 16],
                    acc[i][j], 128, wmma::mem_row_major);
    } else {
        #pragma unroll
        for (int i = 0; i < 2; i++)
            #pragma unroll
            for (int j = 0; j < 2; j++)
                wmma::store_matrix_sync(&outb[(wr * 32 + i * 16) * FO_STR + wc * 32 + j * 16],
                                        acc[i][j], FO_STR, wmma::mem_row_major);
        __syncthreads();
        int grow = row0 + ep_r;
        if (grow < n) {
            float* op = &out[(size_t)grow * 128];
            #pragma unroll
            for (int c = 0; c < 32; c += 4) {
                int cc = ep_c0 + c;
                float4 o = *(const float4*)&outb[ep_r * FO_STR + cc];
                *(float4*)&op[cc] = o;
            }
        }
    }
}

// ---------------- launch ----------------------------------------------------
extern "C" void kernel_launch(void* const* d_in, const int* in_sizes, int n_in,
                              void* d_out, int out_size) {
    const float* x   = (const float*)d_in[0];
    const void*  ids = d_in[1];
    // d_in[2] = total_buckets (constant 8192, unused)
    const float *Wq = (const float*)d_in[3],  *bq = (const float*)d_in[4];
    const float *Wk = (const float*)d_in[5],  *bk = (const float*)d_in[6];
    const float *Wv = (const float*)d_in[7],  *bv = (const float*)d_in[8];
    const float *Wg1 = (const float*)d_in[9], *bg1 = (const float*)d_in[10];
    const float *Wg2 = (const float*)d_in[11], *bg2 = (const float*)d_in[12];
    const float *Wvc = (const float*)d_in[13], *bvc = (const float*)d_in[14];
    const float *Wp  = (const float*)d_in[15], *bp  = (const float*)d_in[16];
    float* out = (float*)d_out;

    const int n = in_sizes[0] / CC;

    static int smem_set = 0;
    if (!smem_set) {
        cudaFuncSetAttribute(k_qkv,   cudaFuncAttributeMaxDynamicSharedMemorySize, SM_QKV_BYTES);
        cudaFuncSetAttribute(k_fused, cudaFuncAttributeMaxDynamicSharedMemorySize, SM_FUSED_BYTES);
        smem_set = 1;
    }

    k_init<<<512, 256>>>();
    k_detect<<<256, 256>>>((const unsigned*)ids, in_sizes[1]);
    k_prep<<<496, 256>>>(Wq, Wk, Wv, Wg1, Wg2, Wp, bq, bk, bv, bg1, bg2, bp);

    int gq = (n + 127) / 128;
    k_qkv<<<gq, 256, SM_QKV_BYTES>>>(x, ids, n);

    k_cent<<<BKT / 2, 256>>>(Wk, bk, Wv, bv, Wvc, bvc);

    int gf = (n + 63) / 64;
    k_fused<<<gf, 256, SM_FUSED_BYTES>>>(ids, out, n);
}